// round 2
// baseline (speedup 1.0000x reference)
#include <cuda_runtime.h>

// Problem constants
#define S_LEN  2048
#define DHEAD  64
#define NHEAD  16
#define NBATCH 2
#define BM     64
#define BN     64
#define TBL    4096   // bias table entries per head, indexed by (i - j) + 2048

// Precomputed bias per (head, i-j)
__device__ float g_bias_delta[NHEAD * TBL];

// ---------------------------------------------------------------------------
// Init kernel: T5 relative-position bucket -> bias value, per head and delta.
// Mirrors the JAX float32 arithmetic exactly:
//   val = log(n/16)/log(16) * 16  (f32 ops, f64 log(16) constant rounded to f32)
// ---------------------------------------------------------------------------
__global__ void bias_init_kernel(const float* __restrict__ bias_table) {
    int idx = blockIdx.x * blockDim.x + threadIdx.x;
    if (idx >= NHEAD * TBL) return;
    int h = idx / TBL;
    int n = (idx % TBL) - 2048;  // n = i - j
    int bucket;
    if (n <= 0) {
        bucket = 0;
    } else if (n < 16) {
        bucket = n;
    } else {
        float vf = logf((float)n / 16.0f) / 2.7725887222397811f * 16.0f;
        vf = fminf(vf, 15.0f);
        bucket = 16 + (int)vf;  // truncation toward zero, vf >= 0 here
    }
    g_bias_delta[idx] = bias_table[bucket * NHEAD + h];
}

// ---------------------------------------------------------------------------
// Flash attention, fp32, one CTA = 64 query rows of one (b, h).
// 256 threads as 16x16: thread (ty,tx) owns rows 4*ty..+3, cols 4*tx..+3.
// smem: sQt[64][64] d-major (pre-scaled by 1/8), sKP[64][68] (K^T then P),
//       sV[64][64] row-major, sB[128] bias window.
// ---------------------------------------------------------------------------
__global__ void __launch_bounds__(256)
attn_kernel(const float* __restrict__ q, const float* __restrict__ k,
            const float* __restrict__ v,
            const int* __restrict__ event_length_i32,
            float* __restrict__ out) {
    extern __shared__ float sm[];
    float* sQt = sm;                    // 64*64
    float* sKP = sm + 64 * 64;          // 64*68 (phase1: K^T d-major, phase2: P row-major)
    float* sV  = sKP + 64 * 68;         // 64*64
    float* sB  = sV + 64 * 64;          // 128

    const int tid = threadIdx.x;
    const int tx = tid & 15;
    const int ty = tid >> 4;

    const int b  = blockIdx.z;
    const int h  = blockIdx.y;
    const int i0 = blockIdx.x * BM;

    const long long base = ((long long)(b * NHEAD + h)) * S_LEN * DHEAD;
    const float* qh = q + base;
    const float* kh = k + base;
    const float* vh = v + base;
    float*       oh = out + base;

    // event_length dtype ambiguity (jax may downcast int64->int32):
    //   int64 layout (LE, values<2^31): [L0, 0, L1, 0] as int32 words
    //   int32 layout:                   [L0, L1]
    // L >= 1 always, so word1==0 <=> int64.
    const int L = (event_length_i32[1] == 0) ? event_length_i32[2 * b]
                                             : event_length_i32[b];
    const int jend = min(S_LEN, ((L + BN - 1) / BN) * BN);

    // Load Q tile transposed (d-major) and pre-scaled by 1/sqrt(D) = 0.125
    #pragma unroll
    for (int it = 0; it < 4; it++) {
        int idx = tid + it * 256;
        int r  = idx >> 4;
        int d4 = (idx & 15) << 2;
        float4 t = *(const float4*)(qh + (i0 + r) * DHEAD + d4);
        sQt[(d4 + 0) * 64 + r] = t.x * 0.125f;
        sQt[(d4 + 1) * 64 + r] = t.y * 0.125f;
        sQt[(d4 + 2) * 64 + r] = t.z * 0.125f;
        sQt[(d4 + 3) * 64 + r] = t.w * 0.125f;
    }

    float m[4], l[4], acc[4][4];
    #pragma unroll
    for (int rr = 0; rr < 4; rr++) {
        m[rr] = -1e30f;
        l[rr] = 0.0f;
        #pragma unroll
        for (int cc = 0; cc < 4; cc++) acc[rr][cc] = 0.0f;
    }

    const float* biasrow = g_bias_delta + h * TBL;

    for (int j0 = 0; j0 < jend; j0 += BN) {
        // --- stage K^T (d-major), V (row-major), bias window ---
        #pragma unroll
        for (int it = 0; it < 4; it++) {
            int idx = tid + it * 256;
            int r  = idx >> 4;
            int d4 = (idx & 15) << 2;
            float4 t = *(const float4*)(kh + (j0 + r) * DHEAD + d4);
            sKP[(d4 + 0) * 68 + r] = t.x;
            sKP[(d4 + 1) * 68 + r] = t.y;
            sKP[(d4 + 2) * 68 + r] = t.z;
            sKP[(d4 + 3) * 68 + r] = t.w;
        }
        #pragma unroll
        for (int it = 0; it < 4; it++) {
            int idx = tid + it * 256;
            ((float4*)sV)[idx] = ((const float4*)(vh + j0 * DHEAD))[idx];
        }
        if (tid < 127) {
            sB[tid] = biasrow[(i0 - j0) + (tid - 63) + 2048];
        }
        __syncthreads();

        // --- S = (Q/8) K^T ---
        float s[4][4];
        #pragma unroll
        for (int rr = 0; rr < 4; rr++)
            #pragma unroll
            for (int cc = 0; cc < 4; cc++) s[rr][cc] = 0.0f;

        #pragma unroll 8
        for (int kk = 0; kk < 64; kk++) {
            float4 qa = *(const float4*)(sQt + kk * 64 + 4 * ty);
            float4 kb = *(const float4*)(sKP + kk * 68 + 4 * tx);
            s[0][0] += qa.x * kb.x; s[0][1] += qa.x * kb.y; s[0][2] += qa.x * kb.z; s[0][3] += qa.x * kb.w;
            s[1][0] += qa.y * kb.x; s[1][1] += qa.y * kb.y; s[1][2] += qa.y * kb.z; s[1][3] += qa.y * kb.w;
            s[2][0] += qa.z * kb.x; s[2][1] += qa.z * kb.y; s[2][2] += qa.z * kb.z; s[2][3] += qa.z * kb.w;
            s[3][0] += qa.w * kb.x; s[3][1] += qa.w * kb.y; s[3][2] += qa.w * kb.z; s[3][3] += qa.w * kb.w;
        }

        // --- bias + key mask (replace with -1e9 like the reference) ---
        #pragma unroll
        for (int rr = 0; rr < 4; rr++) {
            #pragma unroll
            for (int cc = 0; cc < 4; cc++) {
                int jg = j0 + 4 * tx + cc;
                float sv = s[rr][cc] + sB[(4 * ty + rr) - (4 * tx + cc) + 63];
                s[rr][cc] = (jg < L) ? sv : -1e9f;
            }
        }

        // --- online softmax (row stats reduced across tx via shfl) ---
        #pragma unroll
        for (int rr = 0; rr < 4; rr++) {
            float mt = fmaxf(fmaxf(s[rr][0], s[rr][1]), fmaxf(s[rr][2], s[rr][3]));
            mt = fmaxf(mt, __shfl_xor_sync(0xffffffffu, mt, 1));
            mt = fmaxf(mt, __shfl_xor_sync(0xffffffffu, mt, 2));
            mt = fmaxf(mt, __shfl_xor_sync(0xffffffffu, mt, 4));
            mt = fmaxf(mt, __shfl_xor_sync(0xffffffffu, mt, 8));
            float mn = fmaxf(m[rr], mt);
            float sc = __expf(m[rr] - mn);
            float rs = 0.0f;
            #pragma unroll
            for (int cc = 0; cc < 4; cc++) {
                s[rr][cc] = __expf(s[rr][cc] - mn);
                rs += s[rr][cc];
            }
            rs += __shfl_xor_sync(0xffffffffu, rs, 1);
            rs += __shfl_xor_sync(0xffffffffu, rs, 2);
            rs += __shfl_xor_sync(0xffffffffu, rs, 4);
            rs += __shfl_xor_sync(0xffffffffu, rs, 8);
            l[rr] = l[rr] * sc + rs;
            m[rr] = mn;
            #pragma unroll
            for (int cc = 0; cc < 4; cc++) acc[rr][cc] *= sc;
        }

        __syncthreads();  // everyone done reading K^T before P overwrites it

        // --- write P (row-major, padded 68) into the K buffer ---
        #pragma unroll
        for (int rr = 0; rr < 4; rr++) {
            *(float4*)(sKP + (4 * ty + rr) * 68 + 4 * tx) =
                make_float4(s[rr][0], s[rr][1], s[rr][2], s[rr][3]);
        }
        __syncthreads();

        // --- O += P V ---
        #pragma unroll 4
        for (int j = 0; j < 64; j += 4) {
            float4 p0 = *(const float4*)(sKP + (4 * ty + 0) * 68 + j);
            float4 p1 = *(const float4*)(sKP + (4 * ty + 1) * 68 + j);
            float4 p2 = *(const float4*)(sKP + (4 * ty + 2) * 68 + j);
            float4 p3 = *(const float4*)(sKP + (4 * ty + 3) * 68 + j);
            float4 v0 = *(const float4*)(sV + (j + 0) * 64 + 4 * tx);
            float4 v1 = *(const float4*)(sV + (j + 1) * 64 + 4 * tx);
            float4 v2 = *(const float4*)(sV + (j + 2) * 64 + 4 * tx);
            float4 v3 = *(const float4*)(sV + (j + 3) * 64 + 4 * tx);

            acc[0][0] += p0.x * v0.x + p0.y * v1.x + p0.z * v2.x + p0.w * v3.x;
            acc[0][1] += p0.x * v0.y + p0.y * v1.y + p0.z * v2.y + p0.w * v3.y;
            acc[0][2] += p0.x * v0.z + p0.y * v1.z + p0.z * v2.z + p0.w * v3.z;
            acc[0][3] += p0.x * v0.w + p0.y * v1.w + p0.z * v2.w + p0.w * v3.w;

            acc[1][0] += p1.x * v0.x + p1.y * v1.x + p1.z * v2.x + p1.w * v3.x;
            acc[1][1] += p1.x * v0.y + p1.y * v1.y + p1.z * v2.y + p1.w * v3.y;
            acc[1][2] += p1.x * v0.z + p1.y * v1.z + p1.z * v2.z + p1.w * v3.z;
            acc[1][3] += p1.x * v0.w + p1.y * v1.w + p1.z * v2.w + p1.w * v3.w;

            acc[2][0] += p2.x * v0.x + p2.y * v1.x + p2.z * v2.x + p2.w * v3.x;
            acc[2][1] += p2.x * v0.y + p2.y * v1.y + p2.z * v2.y + p2.w * v3.y;
            acc[2][2] += p2.x * v0.z + p2.y * v1.z + p2.z * v2.z + p2.w * v3.z;
            acc[2][3] += p2.x * v0.w + p2.y * v1.w + p2.z * v2.w + p2.w * v3.w;

            acc[3][0] += p3.x * v0.x + p3.y * v1.x + p3.z * v2.x + p3.w * v3.x;
            acc[3][1] += p3.x * v0.y + p3.y * v1.y + p3.z * v2.y + p3.w * v3.y;
            acc[3][2] += p3.x * v0.z + p3.y * v1.z + p3.z * v2.z + p3.w * v3.z;
            acc[3][3] += p3.x * v0.w + p3.y * v1.w + p3.z * v2.w + p3.w * v3.w;
        }
        __syncthreads();  // before next tile reloads sKP / sV
    }

    // --- epilogue: normalize and store ---
    #pragma unroll
    for (int rr = 0; rr < 4; rr++) {
        float inv = 1.0f / l[rr];
        float4 o = make_float4(acc[rr][0] * inv, acc[rr][1] * inv,
                               acc[rr][2] * inv, acc[rr][3] * inv);
        *(float4*)(oh + (i0 + 4 * ty + rr) * DHEAD + 4 * tx) = o;
    }
}

// ---------------------------------------------------------------------------
extern "C" void kernel_launch(void* const* d_in, const int* in_sizes, int n_in,
                              void* d_out, int out_size) {
    const float* q          = (const float*)d_in[0];
    const float* k          = (const float*)d_in[1];
    const float* v          = (const float*)d_in[2];
    const float* bias_table = (const float*)d_in[3];
    const int*   event_len  = (const int*)d_in[4];
    float*       out        = (float*)d_out;

    (void)in_sizes; (void)n_in; (void)out_size;

    bias_init_kernel<<<(NHEAD * TBL + 255) / 256, 256>>>(bias_table);

    const int smem_bytes = (64 * 64 + 64 * 68 + 64 * 64 + 128) * (int)sizeof(float); // 50688
    cudaFuncSetAttribute(attn_kernel, cudaFuncAttributeMaxDynamicSharedMemorySize, smem_bytes);

    dim3 grid(S_LEN / BM, NHEAD, NBATCH);
    attn_kernel<<<grid, 256, smem_bytes>>>(q, k, v, event_len, out);
}

// round 3
// speedup vs baseline: 1.0869x; 1.0869x over previous
#include <cuda_runtime.h>

// Problem constants
#define S_LEN  2048
#define DHEAD  64
#define NHEAD  16
#define NBATCH 2
#define BM     128
#define BN     128
#define TBL    4096   // bias table entries per head, indexed by (i - j) + 2048

// Precomputed bias per (head, i-j)
__device__ float g_bias_delta[NHEAD * TBL];

// ---------------------------------------------------------------------------
// Init kernel: T5 relative-position bucket -> bias value, per head and delta.
// ---------------------------------------------------------------------------
__global__ void bias_init_kernel(const float* __restrict__ bias_table) {
    int idx = blockIdx.x * blockDim.x + threadIdx.x;
    if (idx >= NHEAD * TBL) return;
    int h = idx / TBL;
    int n = (idx % TBL) - 2048;  // n = i - j
    int bucket;
    if (n <= 0) {
        bucket = 0;
    } else if (n < 16) {
        bucket = n;
    } else {
        float vf = logf((float)n / 16.0f) / 2.7725887222397811f * 16.0f;
        vf = fminf(vf, 15.0f);
        bucket = 16 + (int)vf;
    }
    g_bias_delta[idx] = bias_table[bucket * NHEAD + h];
}

// ---------------------------------------------------------------------------
// Flash attention, fp32. One CTA = 128 query rows of one (b,h), key tiles of 128.
// 256 threads as 16x16: thread (ty,tx) owns rows 8*ty..+7.
//   S phase: cols 8*tx..+7 (8x8 micro-tile -> 64 FFMA per 4 LDS.128)
//   O phase: d-cols 4*tx..+3 (8x4 micro-tile)
// smem: sQt[64][132] d-major (pre-scaled), sKP (K^T [64][132], then P [128][132]),
//       sV[128][68] row-major, sB[256] bias window.
// ---------------------------------------------------------------------------
__global__ void __launch_bounds__(256, 1)
attn_kernel(const float* __restrict__ q, const float* __restrict__ k,
            const float* __restrict__ v,
            const int* __restrict__ event_length_i32,
            float* __restrict__ out) {
    extern __shared__ float sm[];
    float* sQt = sm;                       // 64*132
    float* sKP = sm + 64 * 132;            // 128*132 (K^T uses first 64 rows; P uses all)
    float* sV  = sKP + 128 * 132;          // 128*68
    float* sB  = sV + 128 * 68;            // 256

    const int tid = threadIdx.x;
    const int tx = tid & 15;
    const int ty = tid >> 4;

    const int b  = blockIdx.z;
    const int h  = blockIdx.y;
    const int i0 = blockIdx.x * BM;

    const long long base = ((long long)(b * NHEAD + h)) * S_LEN * DHEAD;
    const float* qh = q + base;
    const float* kh = k + base;
    const float* vh = v + base;
    float*       oh = out + base;

    // event_length dtype ambiguity (int64 LE with values<2^31 -> [L0,0,L1,0])
    const int L = (event_length_i32[1] == 0) ? event_length_i32[2 * b]
                                             : event_length_i32[b];
    const int jend = min(S_LEN, ((L + BN - 1) / BN) * BN);

    // Load Q tile transposed (d-major), pre-scaled by 1/sqrt(64) = 0.125
    #pragma unroll
    for (int it = 0; it < 8; it++) {
        int idx = tid + it * 256;          // 0..2047 = 128 rows * 16 float4
        int r  = idx >> 4;
        int d4 = (idx & 15) << 2;
        float4 t = *(const float4*)(qh + (i0 + r) * DHEAD + d4);
        sQt[(d4 + 0) * 132 + r] = t.x * 0.125f;
        sQt[(d4 + 1) * 132 + r] = t.y * 0.125f;
        sQt[(d4 + 2) * 132 + r] = t.z * 0.125f;
        sQt[(d4 + 3) * 132 + r] = t.w * 0.125f;
    }

    float m[8], l[8], o[8][4];
    #pragma unroll
    for (int rr = 0; rr < 8; rr++) {
        m[rr] = -1e30f;
        l[rr] = 0.0f;
        #pragma unroll
        for (int dc = 0; dc < 4; dc++) o[rr][dc] = 0.0f;
    }

    const float* biasrow = g_bias_delta + h * TBL + 2048;

    for (int j0 = 0; j0 < jend; j0 += BN) {
        // --- stage K^T (d-major), V (row-major, pad 68), bias window ---
        #pragma unroll
        for (int it = 0; it < 8; it++) {
            int idx = tid + it * 256;
            int r  = idx >> 4;
            int d4 = (idx & 15) << 2;
            float4 t = *(const float4*)(kh + (j0 + r) * DHEAD + d4);
            sKP[(d4 + 0) * 132 + r] = t.x;
            sKP[(d4 + 1) * 132 + r] = t.y;
            sKP[(d4 + 2) * 132 + r] = t.z;
            sKP[(d4 + 3) * 132 + r] = t.w;
        }
        #pragma unroll
        for (int it = 0; it < 8; it++) {
            int idx = tid + it * 256;
            int r  = idx >> 4;
            int d4 = (idx & 15) << 2;
            *(float4*)(sV + r * 68 + d4) =
                *(const float4*)(vh + (j0 + r) * DHEAD + d4);
        }
        if (tid < 255) {
            sB[tid] = biasrow[(i0 - j0) + (tid - 127)];
        }
        __syncthreads();

        // --- S = (Q/8) K^T : 8x8 micro-tile ---
        float s[8][8];
        #pragma unroll
        for (int rr = 0; rr < 8; rr++)
            #pragma unroll
            for (int cc = 0; cc < 8; cc++) s[rr][cc] = 0.0f;

        #pragma unroll 4
        for (int kk = 0; kk < 64; kk++) {
            float4 qa0 = *(const float4*)(sQt + kk * 132 + 8 * ty);
            float4 qa1 = *(const float4*)(sQt + kk * 132 + 8 * ty + 4);
            float4 kb0 = *(const float4*)(sKP + kk * 132 + 8 * tx);
            float4 kb1 = *(const float4*)(sKP + kk * 132 + 8 * tx + 4);
            float qv[8] = {qa0.x, qa0.y, qa0.z, qa0.w, qa1.x, qa1.y, qa1.z, qa1.w};
            float kv[8] = {kb0.x, kb0.y, kb0.z, kb0.w, kb1.x, kb1.y, kb1.z, kb1.w};
            #pragma unroll
            for (int rr = 0; rr < 8; rr++)
                #pragma unroll
                for (int cc = 0; cc < 8; cc++)
                    s[rr][cc] += qv[rr] * kv[cc];
        }

        // --- bias + key mask ---
        #pragma unroll
        for (int rr = 0; rr < 8; rr++) {
            #pragma unroll
            for (int cc = 0; cc < 8; cc++) {
                int jg = j0 + 8 * tx + cc;
                float sv = s[rr][cc] + sB[(8 * ty + rr) - (8 * tx + cc) + 127];
                s[rr][cc] = (jg < L) ? sv : -1e9f;
            }
        }

        // --- online softmax (row stats across tx via shfl; lane = (ty&1)*16+tx) ---
        #pragma unroll
        for (int rr = 0; rr < 8; rr++) {
            float mt = s[rr][0];
            #pragma unroll
            for (int cc = 1; cc < 8; cc++) mt = fmaxf(mt, s[rr][cc]);
            mt = fmaxf(mt, __shfl_xor_sync(0xffffffffu, mt, 1));
            mt = fmaxf(mt, __shfl_xor_sync(0xffffffffu, mt, 2));
            mt = fmaxf(mt, __shfl_xor_sync(0xffffffffu, mt, 4));
            mt = fmaxf(mt, __shfl_xor_sync(0xffffffffu, mt, 8));
            float mn = fmaxf(m[rr], mt);
            float sc = __expf(m[rr] - mn);
            float rs = 0.0f;
            #pragma unroll
            for (int cc = 0; cc < 8; cc++) {
                s[rr][cc] = __expf(s[rr][cc] - mn);
                rs += s[rr][cc];
            }
            rs += __shfl_xor_sync(0xffffffffu, rs, 1);
            rs += __shfl_xor_sync(0xffffffffu, rs, 2);
            rs += __shfl_xor_sync(0xffffffffu, rs, 4);
            rs += __shfl_xor_sync(0xffffffffu, rs, 8);
            l[rr] = l[rr] * sc + rs;
            m[rr] = mn;
            #pragma unroll
            for (int dc = 0; dc < 4; dc++) o[rr][dc] *= sc;
        }

        __syncthreads();  // done reading K^T before P overwrites it

        // --- write P (row-major, stride 132) into the K buffer ---
        #pragma unroll
        for (int rr = 0; rr < 8; rr++) {
            *(float4*)(sKP + (8 * ty + rr) * 132 + 8 * tx) =
                make_float4(s[rr][0], s[rr][1], s[rr][2], s[rr][3]);
            *(float4*)(sKP + (8 * ty + rr) * 132 + 8 * tx + 4) =
                make_float4(s[rr][4], s[rr][5], s[rr][6], s[rr][7]);
        }
        __syncthreads();

        // --- O += P V : 8 rows x 4 d-cols per thread, j in chunks of 4 ---
        #pragma unroll 2
        for (int j = 0; j < BN; j += 4) {
            float4 p[8];
            #pragma unroll
            for (int rr = 0; rr < 8; rr++)
                p[rr] = *(const float4*)(sKP + (8 * ty + rr) * 132 + j);
            float4 v0 = *(const float4*)(sV + (j + 0) * 68 + 4 * tx);
            float4 v1 = *(const float4*)(sV + (j + 1) * 68 + 4 * tx);
            float4 v2 = *(const float4*)(sV + (j + 2) * 68 + 4 * tx);
            float4 v3 = *(const float4*)(sV + (j + 3) * 68 + 4 * tx);
            #pragma unroll
            for (int rr = 0; rr < 8; rr++) {
                o[rr][0] += p[rr].x * v0.x + p[rr].y * v1.x + p[rr].z * v2.x + p[rr].w * v3.x;
                o[rr][1] += p[rr].x * v0.y + p[rr].y * v1.y + p[rr].z * v2.y + p[rr].w * v3.y;
                o[rr][2] += p[rr].x * v0.z + p[rr].y * v1.z + p[rr].z * v2.z + p[rr].w * v3.z;
                o[rr][3] += p[rr].x * v0.w + p[rr].y * v1.w + p[rr].z * v2.w + p[rr].w * v3.w;
            }
        }
        __syncthreads();  // before next tile reloads sKP / sV
    }

    // --- epilogue: normalize and store ---
    #pragma unroll
    for (int rr = 0; rr < 8; rr++) {
        float inv = 1.0f / l[rr];
        float4 ov = make_float4(o[rr][0] * inv, o[rr][1] * inv,
                                o[rr][2] * inv, o[rr][3] * inv);
        *(float4*)(oh + (i0 + 8 * ty + rr) * DHEAD + 4 * tx) = ov;
    }
}

// ---------------------------------------------------------------------------
extern "C" void kernel_launch(void* const* d_in, const int* in_sizes, int n_in,
                              void* d_out, int out_size) {
    const float* q          = (const float*)d_in[0];
    const float* k          = (const float*)d_in[1];
    const float* v          = (const float*)d_in[2];
    const float* bias_table = (const float*)d_in[3];
    const int*   event_len  = (const int*)d_in[4];
    float*       out        = (float*)d_out;

    (void)in_sizes; (void)n_in; (void)out_size;

    bias_init_kernel<<<(NHEAD * TBL + 255) / 256, 256>>>(bias_table);

    const int smem_bytes = (64 * 132 + 128 * 132 + 128 * 68 + 256) * (int)sizeof(float); // 137216
    cudaFuncSetAttribute(attn_kernel, cudaFuncAttributeMaxDynamicSharedMemorySize, smem_bytes);

    dim3 grid(S_LEN / BM, NHEAD, NBATCH);
    attn_kernel<<<grid, 256, smem_bytes>>>(q, k, v, event_len, out);
}

// round 5
// speedup vs baseline: 3.2872x; 3.0244x over previous
#include <cuda_runtime.h>
#include <cuda_bf16.h>
#include <cstdint>

// Problem constants
#define S_LEN  2048
#define DHEAD  64
#define NHEAD  16
#define NBATCH 2
#define BM     128
#define BN     128
#define TBL    4096

// ---------------------------------------------------------------------------
// Precomputed bias per (head, i-j)
// ---------------------------------------------------------------------------
__device__ float g_bias_delta[NHEAD * TBL];

__global__ void bias_init_kernel(const float* __restrict__ bias_table) {
    int idx = blockIdx.x * blockDim.x + threadIdx.x;
    if (idx >= NHEAD * TBL) return;
    int h = idx / TBL;
    int n = (idx % TBL) - 2048;  // n = i - j
    int bucket;
    if (n <= 0) {
        bucket = 0;
    } else if (n < 16) {
        bucket = n;
    } else {
        float vf = logf((float)n / 16.0f) / 2.7725887222397811f * 16.0f;
        vf = fminf(vf, 15.0f);
        bucket = 16 + (int)vf;
    }
    g_bias_delta[idx] = bias_table[bucket * NHEAD + h];
}

// ---------------------------------------------------------------------------
// MMA / ldmatrix helpers (portable PTX, runs on plain sm_103 target)
// ---------------------------------------------------------------------------
__device__ __forceinline__ uint32_t smem_u32(const void* p) {
    uint32_t a;
    asm("{ .reg .u64 t; cvta.to.shared.u64 t, %1; cvt.u32.u64 %0, t; }" : "=r"(a) : "l"(p));
    return a;
}

#define MMA16816(d, a, b0v, b1v) \
    asm volatile("mma.sync.aligned.m16n8k16.row.col.f32.bf16.bf16.f32 " \
        "{%0,%1,%2,%3}, {%4,%5,%6,%7}, {%8,%9}, {%0,%1,%2,%3};" \
        : "+f"((d)[0]), "+f"((d)[1]), "+f"((d)[2]), "+f"((d)[3]) \
        : "r"((a)[0]), "r"((a)[1]), "r"((a)[2]), "r"((a)[3]), "r"(b0v), "r"(b1v))

#define LDSM4(r, addr) \
    asm volatile("ldmatrix.sync.aligned.m8n8.x4.shared.b16 {%0,%1,%2,%3}, [%4];" \
        : "=r"((r)[0]), "=r"((r)[1]), "=r"((r)[2]), "=r"((r)[3]) : "r"(addr))

#define LDSM4T(r, addr) \
    asm volatile("ldmatrix.sync.aligned.m8n8.x4.trans.shared.b16 {%0,%1,%2,%3}, [%4];" \
        : "=r"((r)[0]), "=r"((r)[1]), "=r"((r)[2]), "=r"((r)[3]) : "r"(addr))

// pack two f32 into bf16x2: low half = lo, high half = hi (first src -> high)
__device__ __forceinline__ uint32_t packbf(float lo, float hi) {
    uint32_t r;
    asm("cvt.rn.bf16x2.f32 %0, %1, %2;" : "=r"(r) : "f"(hi), "f"(lo));
    return r;
}

// Split a float4 into bf16 hi pairs + bf16 residual pairs, store 8B each.
__device__ __forceinline__ void split_store(char* baseHi, char* baseLo,
                                            uint32_t off, float4 t) {
    uint32_t h0 = packbf(t.x, t.y);
    uint32_t h1 = packbf(t.z, t.w);
    float rx = t.x - __uint_as_float(h0 << 16);
    float ry = t.y - __uint_as_float(h0 & 0xFFFF0000u);
    float rz = t.z - __uint_as_float(h1 << 16);
    float rw = t.w - __uint_as_float(h1 & 0xFFFF0000u);
    uint32_t l0 = packbf(rx, ry);
    uint32_t l1 = packbf(rz, rw);
    *(uint2*)(baseHi + off) = make_uint2(h0, h1);
    *(uint2*)(baseLo + off) = make_uint2(l0, l1);
}

// ---------------------------------------------------------------------------
// SMEM layout: halves, row stride 72 (144B -> ldmatrix conflict-free)
// K/V tiles 128 rows x 64 cols (hi & lo). Q staged transiently in V region.
// ---------------------------------------------------------------------------
#define KSTR 72
#define OFF_KHI  0
#define OFF_KLO  18432
#define OFF_VHI  36864
#define OFF_VLO  55296
#define OFF_BIAS 73728   // 256 floats
#define SMEM_TOTAL (73728 + 1024)

// ---------------------------------------------------------------------------
// One CTA = 128 query rows of one (b,h). 8 warps; warp w owns rows 16w..16w+15.
// ---------------------------------------------------------------------------
__global__ void __launch_bounds__(256, 1)
attn_mma_kernel(const float* __restrict__ q, const float* __restrict__ k,
                const float* __restrict__ v,
                const int* __restrict__ event_length_i32,
                float* __restrict__ out) {
    extern __shared__ char smem[];
    const uint32_t sb = smem_u32(smem);

    const int tid = threadIdx.x;
    const int w   = tid >> 5;
    const int l   = tid & 31;
    const int qr  = l >> 2;          // 0..7
    const int qc2 = (l & 3) * 2;     // 0,2,4,6
    const int g   = l >> 3;          // ldmatrix lane group
    const int gr  = l & 7;

    const int b  = blockIdx.z;
    const int h  = blockIdx.y;
    const int i0 = blockIdx.x * BM;

    const long long base = ((long long)(b * NHEAD + h)) * S_LEN * DHEAD;
    const float* qh = q + base;
    const float* kh = k + base;
    const float* vh = v + base;
    float*       oh = out + base;

    const int L = (event_length_i32[1] == 0) ? event_length_i32[2 * b]
                                             : event_length_i32[b];
    const int jend = min(S_LEN, ((L + BN - 1) / BN) * BN);

    // --- stage Q (scaled by 1/8) into V region, extract A-frags to regs ---
    #pragma unroll
    for (int it = 0; it < 8; it++) {
        int idx = tid + it * 256;       // 128 rows * 16 float4
        int row = idx >> 4;
        int d4  = (idx & 15) << 2;
        float4 t = *(const float4*)(qh + (i0 + row) * DHEAD + d4);
        t.x *= 0.125f; t.y *= 0.125f; t.z *= 0.125f; t.w *= 0.125f;
        split_store(smem + OFF_VHI, smem + OFF_VLO, (row * KSTR + d4) * 2, t);
    }
    __syncthreads();

    uint32_t qhi[4][4], qlo[4][4];
    {
        int arow = 16 * w + ((g & 1) << 3) + gr;
        #pragma unroll
        for (int kk = 0; kk < 4; kk++) {
            int ad = 16 * kk + ((g >> 1) << 3);
            uint32_t off = (uint32_t)(arow * KSTR + ad) * 2;
            LDSM4(qhi[kk], sb + OFF_VHI + off);
            LDSM4(qlo[kk], sb + OFF_VLO + off);
        }
    }
    __syncthreads();

    float oacc[32];
    #pragma unroll
    for (int i = 0; i < 32; i++) oacc[i] = 0.0f;
    float m0 = -1e30f, m1 = -1e30f, l0s = 0.0f, l1s = 0.0f;

    const float* biasrow = g_bias_delta + h * TBL + 2048;
    float* sB = (float*)(smem + OFF_BIAS);
    const int ri0 = 16 * w + qr;     // tile-local row of c0/c1

    for (int j0 = 0; j0 < jend; j0 += BN) {
        // --- stage K, V (hi/lo split), bias window ---
        #pragma unroll
        for (int it = 0; it < 8; it++) {
            int idx = tid + it * 256;
            int row = idx >> 4;
            int d4  = (idx & 15) << 2;
            uint32_t off = (uint32_t)(row * KSTR + d4) * 2;
            float4 t = *(const float4*)(kh + (j0 + row) * DHEAD + d4);
            split_store(smem + OFF_KHI, smem + OFF_KLO, off, t);
            float4 u = *(const float4*)(vh + (j0 + row) * DHEAD + d4);
            split_store(smem + OFF_VHI, smem + OFF_VLO, off, u);
        }
        if (tid < 255) sB[tid] = biasrow[(i0 - j0) + (tid - 127)];
        __syncthreads();

        // --- S = Q K^T (hi*hi + hi*lo + lo*hi) ---
        float sacc[64];
        #pragma unroll
        for (int i = 0; i < 64; i++) sacc[i] = 0.0f;

        #pragma unroll
        for (int kk = 0; kk < 4; kk++) {
            #pragma unroll
            for (int t2 = 0; t2 < 8; t2++) {
                int key = 16 * t2 + ((g >> 1) << 3) + gr;
                int d0  = 16 * kk + ((g & 1) << 3);
                uint32_t off = (uint32_t)(key * KSTR + d0) * 2;
                uint32_t kb[4], kl[4];
                LDSM4(kb, sb + OFF_KHI + off);
                LDSM4(kl, sb + OFF_KLO + off);
                float* dA = sacc + 8 * t2;
                float* dB = sacc + 8 * t2 + 4;
                MMA16816(dA, qhi[kk], kb[0], kb[1]);
                MMA16816(dB, qhi[kk], kb[2], kb[3]);
                MMA16816(dA, qhi[kk], kl[0], kl[1]);
                MMA16816(dB, qhi[kk], kl[2], kl[3]);
                MMA16816(dA, qlo[kk], kb[0], kb[1]);
                MMA16816(dB, qlo[kk], kb[2], kb[3]);
            }
        }

        // --- bias + key mask ---
        #pragma unroll
        for (int n = 0; n < 16; n++) {
            int cj = 8 * n + qc2;
            bool in0 = (j0 + cj)     < L;
            bool in1 = (j0 + cj + 1) < L;
            float b00 = sB[ri0 - cj + 127];
            float b01 = sB[ri0 - cj + 126];
            float b10 = sB[ri0 - cj + 135];
            float b11 = sB[ri0 - cj + 134];
            sacc[4 * n + 0] = in0 ? sacc[4 * n + 0] + b00 : -1e9f;
            sacc[4 * n + 1] = in1 ? sacc[4 * n + 1] + b01 : -1e9f;
            sacc[4 * n + 2] = in0 ? sacc[4 * n + 2] + b10 : -1e9f;
            sacc[4 * n + 3] = in1 ? sacc[4 * n + 3] + b11 : -1e9f;
        }

        // --- online softmax (rows live entirely inside the warp quad) ---
        float mx0 = -1e30f, mx1 = -1e30f;
        #pragma unroll
        for (int n = 0; n < 16; n++) {
            mx0 = fmaxf(mx0, fmaxf(sacc[4 * n + 0], sacc[4 * n + 1]));
            mx1 = fmaxf(mx1, fmaxf(sacc[4 * n + 2], sacc[4 * n + 3]));
        }
        mx0 = fmaxf(mx0, __shfl_xor_sync(0xffffffffu, mx0, 1));
        mx0 = fmaxf(mx0, __shfl_xor_sync(0xffffffffu, mx0, 2));
        mx1 = fmaxf(mx1, __shfl_xor_sync(0xffffffffu, mx1, 1));
        mx1 = fmaxf(mx1, __shfl_xor_sync(0xffffffffu, mx1, 2));

        float mn0 = fmaxf(m0, mx0), mn1 = fmaxf(m1, mx1);
        float sc0 = __expf(m0 - mn0), sc1 = __expf(m1 - mn1);
        float rs0 = 0.0f, rs1 = 0.0f;
        #pragma unroll
        for (int n = 0; n < 16; n++) {
            sacc[4 * n + 0] = __expf(sacc[4 * n + 0] - mn0);
            sacc[4 * n + 1] = __expf(sacc[4 * n + 1] - mn0);
            sacc[4 * n + 2] = __expf(sacc[4 * n + 2] - mn1);
            sacc[4 * n + 3] = __expf(sacc[4 * n + 3] - mn1);
            rs0 += sacc[4 * n + 0] + sacc[4 * n + 1];
            rs1 += sacc[4 * n + 2] + sacc[4 * n + 3];
        }
        rs0 += __shfl_xor_sync(0xffffffffu, rs0, 1);
        rs0 += __shfl_xor_sync(0xffffffffu, rs0, 2);
        rs1 += __shfl_xor_sync(0xffffffffu, rs1, 1);
        rs1 += __shfl_xor_sync(0xffffffffu, rs1, 2);
        l0s = l0s * sc0 + rs0;  m0 = mn0;
        l1s = l1s * sc1 + rs1;  m1 = mn1;
        #pragma unroll
        for (int i = 0; i < 8; i++) {
            oacc[4 * i + 0] *= sc0;
            oacc[4 * i + 1] *= sc0;
            oacc[4 * i + 2] *= sc1;
            oacc[4 * i + 3] *= sc1;
        }

        // --- O += P V (P frags built in registers, hi/lo split) ---
        #pragma unroll
        for (int kk2 = 0; kk2 < 8; kk2++) {
            float* pa = sacc + 8 * kk2;        // ntiles 2*kk2, 2*kk2+1
            uint32_t phi[4], plo[4];
            phi[0] = packbf(pa[0], pa[1]);
            phi[1] = packbf(pa[2], pa[3]);
            phi[2] = packbf(pa[4], pa[5]);
            phi[3] = packbf(pa[6], pa[7]);
            plo[0] = packbf(pa[0] - __uint_as_float(phi[0] << 16),
                            pa[1] - __uint_as_float(phi[0] & 0xFFFF0000u));
            plo[1] = packbf(pa[2] - __uint_as_float(phi[1] << 16),
                            pa[3] - __uint_as_float(phi[1] & 0xFFFF0000u));
            plo[2] = packbf(pa[4] - __uint_as_float(phi[2] << 16),
                            pa[5] - __uint_as_float(phi[2] & 0xFFFF0000u));
            plo[3] = packbf(pa[6] - __uint_as_float(phi[3] << 16),
                            pa[7] - __uint_as_float(phi[3] & 0xFFFF0000u));

            int key = 16 * kk2 + ((g & 1) << 3) + gr;
            #pragma unroll
            for (int t2 = 0; t2 < 4; t2++) {
                int d0 = 16 * t2 + ((g >> 1) << 3);
                uint32_t off = (uint32_t)(key * KSTR + d0) * 2;
                uint32_t vb[4], vl[4];
                LDSM4T(vb, sb + OFF_VHI + off);
                LDSM4T(vl, sb + OFF_VLO + off);
                float* oA = oacc + 8 * t2;
                float* oB = oacc + 8 * t2 + 4;
                MMA16816(oA, phi, vb[0], vb[1]);
                MMA16816(oB, phi, vb[2], vb[3]);
                MMA16816(oA, phi, vl[0], vl[1]);
                MMA16816(oB, phi, vl[2], vl[3]);
                MMA16816(oA, plo, vb[0], vb[1]);
                MMA16816(oB, plo, vb[2], vb[3]);
            }
        }
        __syncthreads();   // before next tile overwrites K/V smem
    }

    // --- epilogue: normalize and store ---
    float inv0 = 1.0f / l0s;
    float inv1 = 1.0f / l1s;
    int grow0 = i0 + ri0;
    int grow1 = grow0 + 8;
    #pragma unroll
    for (int n = 0; n < 8; n++) {
        *(float2*)(oh + grow0 * DHEAD + 8 * n + qc2) =
            make_float2(oacc[4 * n + 0] * inv0, oacc[4 * n + 1] * inv0);
        *(float2*)(oh + grow1 * DHEAD + 8 * n + qc2) =
            make_float2(oacc[4 * n + 2] * inv1, oacc[4 * n + 3] * inv1);
    }
}

// ---------------------------------------------------------------------------
extern "C" void kernel_launch(void* const* d_in, const int* in_sizes, int n_in,
                              void* d_out, int out_size) {
    const float* q          = (const float*)d_in[0];
    const float* k          = (const float*)d_in[1];
    const float* v          = (const float*)d_in[2];
    const float* bias_table = (const float*)d_in[3];
    const int*   event_len  = (const int*)d_in[4];
    float*       out        = (float*)d_out;

    (void)in_sizes; (void)n_in; (void)out_size;

    bias_init_kernel<<<(NHEAD * TBL + 255) / 256, 256>>>(bias_table);

    cudaFuncSetAttribute(attn_mma_kernel, cudaFuncAttributeMaxDynamicSharedMemorySize,
                         SMEM_TOTAL);

    dim3 grid(S_LEN / BM, NHEAD, NBATCH);
    attn_mma_kernel<<<grid, 256, SMEM_TOTAL>>>(q, k, v, event_len, out);
}

// round 6
// speedup vs baseline: 3.3674x; 1.0244x over previous
#include <cuda_runtime.h>
#include <cuda_bf16.h>
#include <cstdint>

// Problem constants
#define S_LEN  2048
#define DHEAD  64
#define NHEAD  16
#define NBATCH 2
#define BM     128
#define BN     64
#define TBL    4096

// ---------------------------------------------------------------------------
// Precomputed bias per (head, i-j)
// ---------------------------------------------------------------------------
__device__ float g_bias_delta[NHEAD * TBL];

__global__ void bias_init_kernel(const float* __restrict__ bias_table) {
    int idx = blockIdx.x * blockDim.x + threadIdx.x;
    if (idx >= NHEAD * TBL) return;
    int h = idx / TBL;
    int n = (idx % TBL) - 2048;  // n = i - j
    int bucket;
    if (n <= 0) {
        bucket = 0;
    } else if (n < 16) {
        bucket = n;
    } else {
        float vf = logf((float)n / 16.0f) / 2.7725887222397811f * 16.0f;
        vf = fminf(vf, 15.0f);
        bucket = 16 + (int)vf;
    }
    g_bias_delta[idx] = bias_table[bucket * NHEAD + h];
}

// ---------------------------------------------------------------------------
// MMA / ldmatrix helpers (portable PTX, runs on plain sm_103 target)
// ---------------------------------------------------------------------------
__device__ __forceinline__ uint32_t smem_u32(const void* p) {
    uint32_t a;
    asm("{ .reg .u64 t; cvta.to.shared.u64 t, %1; cvt.u32.u64 %0, t; }" : "=r"(a) : "l"(p));
    return a;
}

#define MMA16816(d, a, b0v, b1v) \
    asm volatile("mma.sync.aligned.m16n8k16.row.col.f32.bf16.bf16.f32 " \
        "{%0,%1,%2,%3}, {%4,%5,%6,%7}, {%8,%9}, {%0,%1,%2,%3};" \
        : "+f"((d)[0]), "+f"((d)[1]), "+f"((d)[2]), "+f"((d)[3]) \
        : "r"((a)[0]), "r"((a)[1]), "r"((a)[2]), "r"((a)[3]), "r"(b0v), "r"(b1v))

#define LDSM4(r, addr) \
    asm volatile("ldmatrix.sync.aligned.m8n8.x4.shared.b16 {%0,%1,%2,%3}, [%4];" \
        : "=r"((r)[0]), "=r"((r)[1]), "=r"((r)[2]), "=r"((r)[3]) : "r"(addr))

#define LDSM4T(r, addr) \
    asm volatile("ldmatrix.sync.aligned.m8n8.x4.trans.shared.b16 {%0,%1,%2,%3}, [%4];" \
        : "=r"((r)[0]), "=r"((r)[1]), "=r"((r)[2]), "=r"((r)[3]) : "r"(addr))

// pack two f32 into bf16x2: low half = first arg, high half = second arg
__device__ __forceinline__ uint32_t packbf(float lo, float hi) {
    uint32_t r;
    asm("cvt.rn.bf16x2.f32 %0, %1, %2;" : "=r"(r) : "f"(hi), "f"(lo));
    return r;
}

// Split a float4 into bf16 hi pairs + bf16 residual pairs, store 8B each.
__device__ __forceinline__ void split_store(char* baseHi, char* baseLo,
                                            uint32_t off, float4 t) {
    uint32_t h0 = packbf(t.x, t.y);
    uint32_t h1 = packbf(t.z, t.w);
    float rx = t.x - __uint_as_float(h0 << 16);
    float ry = t.y - __uint_as_float(h0 & 0xFFFF0000u);
    float rz = t.z - __uint_as_float(h1 << 16);
    float rw = t.w - __uint_as_float(h1 & 0xFFFF0000u);
    uint32_t l0 = packbf(rx, ry);
    uint32_t l1 = packbf(rz, rw);
    *(uint2*)(baseHi + off) = make_uint2(h0, h1);
    *(uint2*)(baseLo + off) = make_uint2(l0, l1);
}

// ---------------------------------------------------------------------------
// SMEM layout, row stride 72 halves (144B -> ldmatrix conflict-free)
// Q persistent 128x64 hi/lo; K/V tiles 64x64 hi/lo; bias window 192 floats.
// ---------------------------------------------------------------------------
#define KSTR 72
#define OFF_QHI  0
#define OFF_QLO  18432
#define OFF_KHI  36864
#define OFF_KLO  46080
#define OFF_VHI  55296
#define OFF_VLO  64512
#define OFF_BIAS 73728
#define SMEM_TOTAL (73728 + 768)

// ---------------------------------------------------------------------------
// One CTA = 128 query rows of one (b,h); 8 warps, warp w owns rows 16w..16w+15.
// Key chunks of 64. Two CTAs per SM for softmax/staging <-> MMA overlap.
// ---------------------------------------------------------------------------
__global__ void __launch_bounds__(256, 2)
attn_mma_kernel(const float* __restrict__ q, const float* __restrict__ k,
                const float* __restrict__ v,
                const int* __restrict__ event_length_i32,
                float* __restrict__ out) {
    extern __shared__ char smem[];
    const uint32_t sb = smem_u32(smem);

    const int tid = threadIdx.x;
    const int w   = tid >> 5;
    const int l   = tid & 31;
    const int qr  = l >> 2;          // 0..7
    const int qc2 = (l & 3) * 2;     // 0,2,4,6
    const int g   = l >> 3;          // ldmatrix lane group
    const int gr  = l & 7;

    const int b  = blockIdx.z;
    const int h  = blockIdx.y;
    const int i0 = blockIdx.x * BM;

    const long long base = ((long long)(b * NHEAD + h)) * S_LEN * DHEAD;
    const float* qh = q + base;
    const float* kh = k + base;
    const float* vh = v + base;
    float*       oh = out + base;

    const int L = (event_length_i32[1] == 0) ? event_length_i32[2 * b]
                                             : event_length_i32[b];
    const int jend = min(S_LEN, ((L + BN - 1) / BN) * BN);

    // --- stage Q (scaled by 1/8) hi/lo into persistent smem region ---
    #pragma unroll
    for (int it = 0; it < 8; it++) {
        int idx = tid + it * 256;       // 128 rows * 16 float4
        int row = idx >> 4;
        int d4  = (idx & 15) << 2;
        float4 t = *(const float4*)(qh + (i0 + row) * DHEAD + d4);
        t.x *= 0.125f; t.y *= 0.125f; t.z *= 0.125f; t.w *= 0.125f;
        split_store(smem + OFF_QHI, smem + OFF_QLO, (row * KSTR + d4) * 2, t);
    }

    float oacc[32];
    #pragma unroll
    for (int i = 0; i < 32; i++) oacc[i] = 0.0f;
    float m0 = -1e30f, m1 = -1e30f, l0s = 0.0f, l1s = 0.0f;

    const float* biasrow = g_bias_delta + h * TBL + 2048;
    float* sB = (float*)(smem + OFF_BIAS);
    const int ri0 = 16 * w + qr;         // tile-local row of c0/c1
    const int arow = 16 * w + ((g & 1) << 3) + gr;  // ldmatrix row for Q frags

    for (int j0 = 0; j0 < jend; j0 += BN) {
        // --- stage K, V (hi/lo split), bias window ---
        #pragma unroll
        for (int it = 0; it < 4; it++) {
            int idx = tid + it * 256;   // 64 rows * 16 float4
            int row = idx >> 4;
            int d4  = (idx & 15) << 2;
            uint32_t off = (uint32_t)(row * KSTR + d4) * 2;
            float4 t = *(const float4*)(kh + (j0 + row) * DHEAD + d4);
            split_store(smem + OFF_KHI, smem + OFF_KLO, off, t);
            float4 u = *(const float4*)(vh + (j0 + row) * DHEAD + d4);
            split_store(smem + OFF_VHI, smem + OFF_VLO, off, u);
        }
        if (tid < 191) sB[tid] = biasrow[(i0 - j0) + (tid - 63)];
        __syncthreads();

        // --- S = Q K^T (hi*hi + hi*lo + lo*hi) ---
        float sacc[32];
        #pragma unroll
        for (int i = 0; i < 32; i++) sacc[i] = 0.0f;

        #pragma unroll
        for (int kk = 0; kk < 4; kk++) {
            int ad = 16 * kk + ((g >> 1) << 3);
            uint32_t qoff = (uint32_t)(arow * KSTR + ad) * 2;
            uint32_t qhif[4], qlof[4];
            LDSM4(qhif, sb + OFF_QHI + qoff);
            LDSM4(qlof, sb + OFF_QLO + qoff);
            #pragma unroll
            for (int t2 = 0; t2 < 4; t2++) {
                int key = 16 * t2 + ((g >> 1) << 3) + gr;
                int d0  = 16 * kk + ((g & 1) << 3);
                uint32_t off = (uint32_t)(key * KSTR + d0) * 2;
                uint32_t kb[4], kl[4];
                LDSM4(kb, sb + OFF_KHI + off);
                LDSM4(kl, sb + OFF_KLO + off);
                float* dA = sacc + 8 * t2;
                float* dB = sacc + 8 * t2 + 4;
                MMA16816(dA, qhif, kb[0], kb[1]);
                MMA16816(dB, qhif, kb[2], kb[3]);
                MMA16816(dA, qhif, kl[0], kl[1]);
                MMA16816(dB, qhif, kl[2], kl[3]);
                MMA16816(dA, qlof, kb[0], kb[1]);
                MMA16816(dB, qlof, kb[2], kb[3]);
            }
        }

        // --- bias + key mask ---
        #pragma unroll
        for (int n = 0; n < 8; n++) {
            int cj = 8 * n + qc2;
            bool in0 = (j0 + cj)     < L;
            bool in1 = (j0 + cj + 1) < L;
            float b00 = sB[ri0 - cj + 63];
            float b01 = sB[ri0 - cj + 62];
            float b10 = sB[ri0 - cj + 71];
            float b11 = sB[ri0 - cj + 70];
            sacc[4 * n + 0] = in0 ? sacc[4 * n + 0] + b00 : -1e9f;
            sacc[4 * n + 1] = in1 ? sacc[4 * n + 1] + b01 : -1e9f;
            sacc[4 * n + 2] = in0 ? sacc[4 * n + 2] + b10 : -1e9f;
            sacc[4 * n + 3] = in1 ? sacc[4 * n + 3] + b11 : -1e9f;
        }

        // --- online softmax (rows live inside the warp quad) ---
        float mx0 = -1e30f, mx1 = -1e30f;
        #pragma unroll
        for (int n = 0; n < 8; n++) {
            mx0 = fmaxf(mx0, fmaxf(sacc[4 * n + 0], sacc[4 * n + 1]));
            mx1 = fmaxf(mx1, fmaxf(sacc[4 * n + 2], sacc[4 * n + 3]));
        }
        mx0 = fmaxf(mx0, __shfl_xor_sync(0xffffffffu, mx0, 1));
        mx0 = fmaxf(mx0, __shfl_xor_sync(0xffffffffu, mx0, 2));
        mx1 = fmaxf(mx1, __shfl_xor_sync(0xffffffffu, mx1, 1));
        mx1 = fmaxf(mx1, __shfl_xor_sync(0xffffffffu, mx1, 2));

        float mn0 = fmaxf(m0, mx0), mn1 = fmaxf(m1, mx1);
        float sc0 = __expf(m0 - mn0), sc1 = __expf(m1 - mn1);
        float rs0 = 0.0f, rs1 = 0.0f;
        #pragma unroll
        for (int n = 0; n < 8; n++) {
            sacc[4 * n + 0] = __expf(sacc[4 * n + 0] - mn0);
            sacc[4 * n + 1] = __expf(sacc[4 * n + 1] - mn0);
            sacc[4 * n + 2] = __expf(sacc[4 * n + 2] - mn1);
            sacc[4 * n + 3] = __expf(sacc[4 * n + 3] - mn1);
            rs0 += sacc[4 * n + 0] + sacc[4 * n + 1];
            rs1 += sacc[4 * n + 2] + sacc[4 * n + 3];
        }
        rs0 += __shfl_xor_sync(0xffffffffu, rs0, 1);
        rs0 += __shfl_xor_sync(0xffffffffu, rs0, 2);
        rs1 += __shfl_xor_sync(0xffffffffu, rs1, 1);
        rs1 += __shfl_xor_sync(0xffffffffu, rs1, 2);
        l0s = l0s * sc0 + rs0;  m0 = mn0;
        l1s = l1s * sc1 + rs1;  m1 = mn1;
        #pragma unroll
        for (int i = 0; i < 8; i++) {
            oacc[4 * i + 0] *= sc0;
            oacc[4 * i + 1] *= sc0;
            oacc[4 * i + 2] *= sc1;
            oacc[4 * i + 3] *= sc1;
        }

        // --- O += P V (P frags built in registers, hi/lo split) ---
        #pragma unroll
        for (int kk2 = 0; kk2 < 4; kk2++) {
            float* pa = sacc + 8 * kk2;
            uint32_t phi[4], plo[4];
            phi[0] = packbf(pa[0], pa[1]);
            phi[1] = packbf(pa[2], pa[3]);
            phi[2] = packbf(pa[4], pa[5]);
            phi[3] = packbf(pa[6], pa[7]);
            plo[0] = packbf(pa[0] - __uint_as_float(phi[0] << 16),
                            pa[1] - __uint_as_float(phi[0] & 0xFFFF0000u));
            plo[1] = packbf(pa[2] - __uint_as_float(phi[1] << 16),
                            pa[3] - __uint_as_float(phi[1] & 0xFFFF0000u));
            plo[2] = packbf(pa[4] - __uint_as_float(phi[2] << 16),
                            pa[5] - __uint_as_float(phi[2] & 0xFFFF0000u));
            plo[3] = packbf(pa[6] - __uint_as_float(phi[3] << 16),
                            pa[7] - __uint_as_float(phi[3] & 0xFFFF0000u));

            int key = 16 * kk2 + ((g & 1) << 3) + gr;
            #pragma unroll
            for (int t2 = 0; t2 < 4; t2++) {
                int d0 = 16 * t2 + ((g >> 1) << 3);
                uint32_t off = (uint32_t)(key * KSTR + d0) * 2;
                uint32_t vb[4], vl[4];
                LDSM4T(vb, sb + OFF_VHI + off);
                LDSM4T(vl, sb + OFF_VLO + off);
                float* oA = oacc + 8 * t2;
                float* oB = oacc + 8 * t2 + 4;
                MMA16816(oA, phi, vb[0], vb[1]);
                MMA16816(oB, phi, vb[2], vb[3]);
                MMA16816(oA, phi, vl[0], vl[1]);
                MMA16816(oB, phi, vl[2], vl[3]);
                MMA16816(oA, plo, vb[0], vb[1]);
                MMA16816(oB, plo, vb[2], vb[3]);
            }
        }
        __syncthreads();   // before next tile overwrites K/V smem
    }

    // --- epilogue: normalize and store ---
    float inv0 = 1.0f / l0s;
    float inv1 = 1.0f / l1s;
    int grow0 = i0 + ri0;
    int grow1 = grow0 + 8;
    #pragma unroll
    for (int n = 0; n < 8; n++) {
        *(float2*)(oh + grow0 * DHEAD + 8 * n + qc2) =
            make_float2(oacc[4 * n + 0] * inv0, oacc[4 * n + 1] * inv0);
        *(float2*)(oh + grow1 * DHEAD + 8 * n + qc2) =
            make_float2(oacc[4 * n + 2] * inv1, oacc[4 * n + 3] * inv1);
    }
}

// ---------------------------------------------------------------------------
extern "C" void kernel_launch(void* const* d_in, const int* in_sizes, int n_in,
                              void* d_out, int out_size) {
    const float* q          = (const float*)d_in[0];
    const float* k          = (const float*)d_in[1];
    const float* v          = (const float*)d_in[2];
    const float* bias_table = (const float*)d_in[3];
    const int*   event_len  = (const int*)d_in[4];
    float*       out        = (float*)d_out;

    (void)in_sizes; (void)n_in; (void)out_size;

    bias_init_kernel<<<(NHEAD * TBL + 255) / 256, 256>>>(bias_table);

    cudaFuncSetAttribute(attn_mma_kernel, cudaFuncAttributeMaxDynamicSharedMemorySize,
                         SMEM_TOTAL);

    dim3 grid(S_LEN / BM, NHEAD, NBATCH);
    attn_mma_kernel<<<grid, 256, SMEM_TOTAL>>>(q, k, v, event_len, out);
}

// round 7
// speedup vs baseline: 3.9648x; 1.1774x over previous
#include <cuda_runtime.h>
#include <cuda_fp16.h>
#include <cstdint>

// Problem constants
#define S_LEN  2048
#define DHEAD  64
#define NHEAD  16
#define NBATCH 2
#define BM     128
#define BN     64
#define TBL    4096

// ---------------------------------------------------------------------------
// Precomputed bias per (head, i-j)
// ---------------------------------------------------------------------------
__device__ float g_bias_delta[NHEAD * TBL];

__global__ void bias_init_kernel(const float* __restrict__ bias_table) {
    int idx = blockIdx.x * blockDim.x + threadIdx.x;
    if (idx >= NHEAD * TBL) return;
    int h = idx / TBL;
    int n = (idx % TBL) - 2048;  // n = i - j
    int bucket;
    if (n <= 0) {
        bucket = 0;
    } else if (n < 16) {
        bucket = n;
    } else {
        float vf = logf((float)n / 16.0f) / 2.7725887222397811f * 16.0f;
        vf = fminf(vf, 15.0f);
        bucket = 16 + (int)vf;
    }
    g_bias_delta[idx] = bias_table[bucket * NHEAD + h];
}

// ---------------------------------------------------------------------------
// Helpers (portable PTX, plain sm_103 target)
// ---------------------------------------------------------------------------
__device__ __forceinline__ uint32_t smem_u32(const void* p) {
    uint32_t a;
    asm("{ .reg .u64 t; cvta.to.shared.u64 t, %1; cvt.u32.u64 %0, t; }" : "=r"(a) : "l"(p));
    return a;
}

#define MMAH(d, a, b0v, b1v) \
    asm volatile("mma.sync.aligned.m16n8k16.row.col.f32.f16.f16.f32 " \
        "{%0,%1,%2,%3}, {%4,%5,%6,%7}, {%8,%9}, {%0,%1,%2,%3};" \
        : "+f"((d)[0]), "+f"((d)[1]), "+f"((d)[2]), "+f"((d)[3]) \
        : "r"((a)[0]), "r"((a)[1]), "r"((a)[2]), "r"((a)[3]), "r"(b0v), "r"(b1v))

#define LDSM4(r, addr) \
    asm volatile("ldmatrix.sync.aligned.m8n8.x4.shared.b16 {%0,%1,%2,%3}, [%4];" \
        : "=r"((r)[0]), "=r"((r)[1]), "=r"((r)[2]), "=r"((r)[3]) : "r"(addr))

#define LDSM4T(r, addr) \
    asm volatile("ldmatrix.sync.aligned.m8n8.x4.trans.shared.b16 {%0,%1,%2,%3}, [%4];" \
        : "=r"((r)[0]), "=r"((r)[1]), "=r"((r)[2]), "=r"((r)[3]) : "r"(addr))

// pack two f32 -> f16x2, first arg -> low half
__device__ __forceinline__ uint32_t packh(float lo, float hi) {
    uint32_t r;
    asm("cvt.rn.f16x2.f32 %0, %1, %2;" : "=r"(r) : "f"(hi), "f"(lo));
    return r;
}
__device__ __forceinline__ uint32_t h2u(__half a, __half b) {
    __half2 t = __halves2half2(a, b);
    return *(uint32_t*)&t;
}

#define CP16(dst, src) \
    asm volatile("cp.async.cg.shared.global [%0], [%1], 16;" :: "r"(dst), "l"(src))
#define CP_COMMIT() asm volatile("cp.async.commit_group;" ::: "memory")
#define CP_WAIT0()  asm volatile("cp.async.wait_group 0;" ::: "memory")

// ---------------------------------------------------------------------------
// SMEM layout (bytes). fp16 tiles: row stride 72 halves (144B, ldmatrix-safe)
// raw fp32 prefetch buffers: row stride 68 floats (272B, conflict-staggered)
// ---------------------------------------------------------------------------
#define KSTR 72
#define OFF_Q    0        // 128*72*2 = 18432
#define OFF_KHI  18432    // 64*72*2 = 9216 each
#define OFF_KLO  27648
#define OFF_VHI  36864
#define OFF_VLO  46080
#define OFF_RAWK 55296    // 64*68*4 = 17408 each
#define OFF_RAWV 72704
#define OFF_BIAS 90112    // 192 floats
#define SMEM_TOTAL 90880

// ---------------------------------------------------------------------------
// One CTA = 128 query rows of one (b,h); 8 warps, warp w owns rows 16w..16w+15.
// Key chunks of 64. fp16 2-term (K,V split hi/lo; Q,P rounded once).
// cp.async prefetches next K/V raw tile during MMA phase.
// ---------------------------------------------------------------------------
__global__ void __launch_bounds__(256, 2)
attn_mma_kernel(const float* __restrict__ q, const float* __restrict__ k,
                const float* __restrict__ v,
                const int* __restrict__ event_length_i32,
                float* __restrict__ out) {
    extern __shared__ char smem[];
    const uint32_t sb = smem_u32(smem);

    const int tid = threadIdx.x;
    const int w   = tid >> 5;
    const int l   = tid & 31;
    const int qr  = l >> 2;          // 0..7
    const int qc2 = (l & 3) * 2;     // 0,2,4,6
    const int g   = l >> 3;          // ldmatrix lane group
    const int gr  = l & 7;

    const int b  = blockIdx.z;
    const int h  = blockIdx.y;
    const int i0 = blockIdx.x * BM;

    const long long base = ((long long)(b * NHEAD + h)) * S_LEN * DHEAD;
    const float* qh = q + base;
    const float* kh = k + base;
    const float* vh = v + base;
    float*       oh = out + base;

    const int L = (event_length_i32[1] == 0) ? event_length_i32[2 * b]
                                             : event_length_i32[b];
    const int jend = min(S_LEN, ((L + BN - 1) / BN) * BN);

    // --- stage Q (scaled by 1/8) single fp16 into persistent smem ---
    #pragma unroll
    for (int it = 0; it < 8; it++) {
        int idx = tid + it * 256;       // 128 rows * 16 float4
        int row = idx >> 4;
        int c4  = (idx & 15) << 2;
        float4 t = *(const float4*)(qh + (i0 + row) * DHEAD + c4);
        t.x *= 0.125f; t.y *= 0.125f; t.z *= 0.125f; t.w *= 0.125f;
        uint32_t u0 = h2u(__float2half_rn(t.x), __float2half_rn(t.y));
        uint32_t u1 = h2u(__float2half_rn(t.z), __float2half_rn(t.w));
        *(uint2*)(smem + OFF_Q + (uint32_t)(row * KSTR + c4) * 2) = make_uint2(u0, u1);
    }

    // --- prefetch tile 0 raw K/V ---
    #pragma unroll
    for (int it = 0; it < 4; it++) {
        int idx = tid + it * 256;       // 64 rows * 16 float4
        int row = idx >> 4;
        int c4  = (idx & 15) << 2;
        uint32_t roff = (uint32_t)(row * 68 + c4) * 4;
        CP16(sb + OFF_RAWK + roff, kh + row * DHEAD + c4);
        CP16(sb + OFF_RAWV + roff, vh + row * DHEAD + c4);
    }
    CP_COMMIT();

    float oacc[32];
    #pragma unroll
    for (int i = 0; i < 32; i++) oacc[i] = 0.0f;
    float m0 = -1e30f, m1 = -1e30f, l0s = 0.0f, l1s = 0.0f;

    const float* biasrow = g_bias_delta + h * TBL + 2048;
    float* sB = (float*)(smem + OFF_BIAS);
    const int ri0  = 16 * w + qr;                    // tile-local row of c0/c1
    const int arow = 16 * w + ((g & 1) << 3) + gr;   // ldmatrix row for Q frags

    for (int j0 = 0; j0 < jend; j0 += BN) {
        CP_WAIT0();
        __syncthreads();   // raw[j] visible everywhere; prev MMAs done with fp16 bufs

        // --- convert raw -> fp16 hi/lo tiles; bias window ---
        #pragma unroll
        for (int it = 0; it < 4; it++) {
            int idx = tid + it * 256;
            int row = idx >> 4;
            int c4  = (idx & 15) << 2;
            uint32_t roff = (uint32_t)(row * 68 + c4) * 4;
            uint32_t soff = (uint32_t)(row * KSTR + c4) * 2;

            float4 t = *(const float4*)(smem + OFF_RAWK + roff);
            __half hx = __float2half_rn(t.x), hy = __float2half_rn(t.y);
            __half hz = __float2half_rn(t.z), hw = __float2half_rn(t.w);
            *(uint2*)(smem + OFF_KHI + soff) = make_uint2(h2u(hx, hy), h2u(hz, hw));
            *(uint2*)(smem + OFF_KLO + soff) = make_uint2(
                h2u(__float2half_rn(t.x - __half2float(hx)),
                    __float2half_rn(t.y - __half2float(hy))),
                h2u(__float2half_rn(t.z - __half2float(hz)),
                    __float2half_rn(t.w - __half2float(hw))));

            float4 u = *(const float4*)(smem + OFF_RAWV + roff);
            __half vx = __float2half_rn(u.x), vy = __float2half_rn(u.y);
            __half vz = __float2half_rn(u.z), vw = __float2half_rn(u.w);
            *(uint2*)(smem + OFF_VHI + soff) = make_uint2(h2u(vx, vy), h2u(vz, vw));
            *(uint2*)(smem + OFF_VLO + soff) = make_uint2(
                h2u(__float2half_rn(u.x - __half2float(vx)),
                    __float2half_rn(u.y - __half2float(vy))),
                h2u(__float2half_rn(u.z - __half2float(vz)),
                    __float2half_rn(u.w - __half2float(vw))));
        }
        if (tid < 191) {
            int di = (i0 - j0) + (tid - 63);
            di = min(2047, max(-2048, di));   // clamp (out-of-window entries unused)
            sB[tid] = biasrow[di];
        }
        __syncthreads();   // fp16 tiles + bias ready; raw buffer free

        // --- prefetch next tile raw K/V (overlaps MMAs below) ---
        if (j0 + BN < jend) {
            const float* kn = kh + (j0 + BN) * DHEAD;
            const float* vn = vh + (j0 + BN) * DHEAD;
            #pragma unroll
            for (int it = 0; it < 4; it++) {
                int idx = tid + it * 256;
                int row = idx >> 4;
                int c4  = (idx & 15) << 2;
                uint32_t roff = (uint32_t)(row * 68 + c4) * 4;
                CP16(sb + OFF_RAWK + roff, kn + row * DHEAD + c4);
                CP16(sb + OFF_RAWV + roff, vn + row * DHEAD + c4);
            }
        }
        CP_COMMIT();

        // --- S = q~ * (Kh + Kl)^T : 2-term fp16 ---
        float sacc[32];
        #pragma unroll
        for (int i = 0; i < 32; i++) sacc[i] = 0.0f;

        #pragma unroll
        for (int kk = 0; kk < 4; kk++) {
            int ad = 16 * kk + ((g >> 1) << 3);
            uint32_t qf[4];
            LDSM4(qf, sb + OFF_Q + (uint32_t)(arow * KSTR + ad) * 2);
            #pragma unroll
            for (int t2 = 0; t2 < 4; t2++) {
                int key = 16 * t2 + ((g >> 1) << 3) + gr;
                int d0  = 16 * kk + ((g & 1) << 3);
                uint32_t off = (uint32_t)(key * KSTR + d0) * 2;
                uint32_t kbh[4], kbl[4];
                LDSM4(kbh, sb + OFF_KHI + off);
                LDSM4(kbl, sb + OFF_KLO + off);
                float* dA = sacc + 8 * t2;
                float* dB = sacc + 8 * t2 + 4;
                MMAH(dA, qf, kbh[0], kbh[1]);
                MMAH(dB, qf, kbh[2], kbh[3]);
                MMAH(dA, qf, kbl[0], kbl[1]);
                MMAH(dB, qf, kbl[2], kbl[3]);
            }
        }

        // --- bias + key mask ---
        #pragma unroll
        for (int n = 0; n < 8; n++) {
            int cj = 8 * n + qc2;
            bool in0 = (j0 + cj)     < L;
            bool in1 = (j0 + cj + 1) < L;
            float b00 = sB[ri0 - cj + 63];
            float b01 = sB[ri0 - cj + 62];
            float b10 = sB[ri0 - cj + 71];
            float b11 = sB[ri0 - cj + 70];
            sacc[4 * n + 0] = in0 ? sacc[4 * n + 0] + b00 : -1e9f;
            sacc[4 * n + 1] = in1 ? sacc[4 * n + 1] + b01 : -1e9f;
            sacc[4 * n + 2] = in0 ? sacc[4 * n + 2] + b10 : -1e9f;
            sacc[4 * n + 3] = in1 ? sacc[4 * n + 3] + b11 : -1e9f;
        }

        // --- online softmax (rows live inside the warp quad) ---
        float mx0 = -1e30f, mx1 = -1e30f;
        #pragma unroll
        for (int n = 0; n < 8; n++) {
            mx0 = fmaxf(mx0, fmaxf(sacc[4 * n + 0], sacc[4 * n + 1]));
            mx1 = fmaxf(mx1, fmaxf(sacc[4 * n + 2], sacc[4 * n + 3]));
        }
        mx0 = fmaxf(mx0, __shfl_xor_sync(0xffffffffu, mx0, 1));
        mx0 = fmaxf(mx0, __shfl_xor_sync(0xffffffffu, mx0, 2));
        mx1 = fmaxf(mx1, __shfl_xor_sync(0xffffffffu, mx1, 1));
        mx1 = fmaxf(mx1, __shfl_xor_sync(0xffffffffu, mx1, 2));

        float mn0 = fmaxf(m0, mx0), mn1 = fmaxf(m1, mx1);
        float sc0 = __expf(m0 - mn0), sc1 = __expf(m1 - mn1);
        float rs0 = 0.0f, rs1 = 0.0f;
        #pragma unroll
        for (int n = 0; n < 8; n++) {
            sacc[4 * n + 0] = __expf(sacc[4 * n + 0] - mn0);
            sacc[4 * n + 1] = __expf(sacc[4 * n + 1] - mn0);
            sacc[4 * n + 2] = __expf(sacc[4 * n + 2] - mn1);
            sacc[4 * n + 3] = __expf(sacc[4 * n + 3] - mn1);
            rs0 += sacc[4 * n + 0] + sacc[4 * n + 1];
            rs1 += sacc[4 * n + 2] + sacc[4 * n + 3];
        }
        rs0 += __shfl_xor_sync(0xffffffffu, rs0, 1);
        rs0 += __shfl_xor_sync(0xffffffffu, rs0, 2);
        rs1 += __shfl_xor_sync(0xffffffffu, rs1, 1);
        rs1 += __shfl_xor_sync(0xffffffffu, rs1, 2);
        l0s = l0s * sc0 + rs0;  m0 = mn0;
        l1s = l1s * sc1 + rs1;  m1 = mn1;
        #pragma unroll
        for (int i = 0; i < 8; i++) {
            oacc[4 * i + 0] *= sc0;
            oacc[4 * i + 1] *= sc0;
            oacc[4 * i + 2] *= sc1;
            oacc[4 * i + 3] *= sc1;
        }

        // --- O += p~ * (Vh + Vl) : 2-term fp16, P frags in registers ---
        #pragma unroll
        for (int kk2 = 0; kk2 < 4; kk2++) {
            float* pa = sacc + 8 * kk2;
            uint32_t phi[4];
            phi[0] = packh(pa[0], pa[1]);
            phi[1] = packh(pa[2], pa[3]);
            phi[2] = packh(pa[4], pa[5]);
            phi[3] = packh(pa[6], pa[7]);

            int key = 16 * kk2 + ((g & 1) << 3) + gr;
            #pragma unroll
            for (int t2 = 0; t2 < 4; t2++) {
                int d0 = 16 * t2 + ((g >> 1) << 3);
                uint32_t off = (uint32_t)(key * KSTR + d0) * 2;
                uint32_t vbh[4], vbl[4];
                LDSM4T(vbh, sb + OFF_VHI + off);
                LDSM4T(vbl, sb + OFF_VLO + off);
                float* oA = oacc + 8 * t2;
                float* oB = oacc + 8 * t2 + 4;
                MMAH(oA, phi, vbh[0], vbh[1]);
                MMAH(oB, phi, vbh[2], vbh[3]);
                MMAH(oA, phi, vbl[0], vbl[1]);
                MMAH(oB, phi, vbl[2], vbl[3]);
            }
        }
    }

    // --- epilogue: normalize and store ---
    float inv0 = 1.0f / l0s;
    float inv1 = 1.0f / l1s;
    int grow0 = i0 + ri0;
    int grow1 = grow0 + 8;
    #pragma unroll
    for (int n = 0; n < 8; n++) {
        *(float2*)(oh + grow0 * DHEAD + 8 * n + qc2) =
            make_float2(oacc[4 * n + 0] * inv0, oacc[4 * n + 1] * inv0);
        *(float2*)(oh + grow1 * DHEAD + 8 * n + qc2) =
            make_float2(oacc[4 * n + 2] * inv1, oacc[4 * n + 3] * inv1);
    }
}

// ---------------------------------------------------------------------------
extern "C" void kernel_launch(void* const* d_in, const int* in_sizes, int n_in,
                              void* d_out, int out_size) {
    const float* q          = (const float*)d_in[0];
    const float* k          = (const float*)d_in[1];
    const float* v          = (const float*)d_in[2];
    const float* bias_table = (const float*)d_in[3];
    const int*   event_len  = (const int*)d_in[4];
    float*       out        = (float*)d_out;

    (void)in_sizes; (void)n_in; (void)out_size;

    bias_init_kernel<<<(NHEAD * TBL + 255) / 256, 256>>>(bias_table);

    cudaFuncSetAttribute(attn_mma_kernel, cudaFuncAttributeMaxDynamicSharedMemorySize,
                         SMEM_TOTAL);

    dim3 grid(S_LEN / BM, NHEAD, NBATCH);
    attn_mma_kernel<<<grid, 256, SMEM_TOTAL>>>(q, k, v, event_len, out);
}

// round 8
// speedup vs baseline: 5.3022x; 1.3373x over previous
#include <cuda_runtime.h>
#include <cuda_fp16.h>
#include <cstdint>

// Problem constants
#define S_LEN  2048
#define DHEAD  64
#define NHEAD  16
#define NBATCH 2
#define BM     128
#define BN     64
#define TBL    4096

// ---------------------------------------------------------------------------
// Precomputed bias per (head, i-j)
// ---------------------------------------------------------------------------
__device__ float g_bias_delta[NHEAD * TBL];

__global__ void bias_init_kernel(const float* __restrict__ bias_table) {
    int idx = blockIdx.x * blockDim.x + threadIdx.x;
    if (idx >= NHEAD * TBL) return;
    int h = idx / TBL;
    int n = (idx % TBL) - 2048;  // n = i - j
    int bucket;
    if (n <= 0) {
        bucket = 0;
    } else if (n < 16) {
        bucket = n;
    } else {
        float vf = logf((float)n / 16.0f) / 2.7725887222397811f * 16.0f;
        vf = fminf(vf, 15.0f);
        bucket = 16 + (int)vf;
    }
    g_bias_delta[idx] = bias_table[bucket * NHEAD + h];
}

// ---------------------------------------------------------------------------
// Helpers (portable PTX, plain sm_103 target)
// ---------------------------------------------------------------------------
__device__ __forceinline__ uint32_t smem_u32(const void* p) {
    uint32_t a;
    asm("{ .reg .u64 t; cvta.to.shared.u64 t, %1; cvt.u32.u64 %0, t; }" : "=r"(a) : "l"(p));
    return a;
}

#define MMAH(d, a, b0v, b1v) \
    asm volatile("mma.sync.aligned.m16n8k16.row.col.f32.f16.f16.f32 " \
        "{%0,%1,%2,%3}, {%4,%5,%6,%7}, {%8,%9}, {%0,%1,%2,%3};" \
        : "+f"((d)[0]), "+f"((d)[1]), "+f"((d)[2]), "+f"((d)[3]) \
        : "r"((a)[0]), "r"((a)[1]), "r"((a)[2]), "r"((a)[3]), "r"(b0v), "r"(b1v))

#define LDSM4(r, addr) \
    asm volatile("ldmatrix.sync.aligned.m8n8.x4.shared.b16 {%0,%1,%2,%3}, [%4];" \
        : "=r"((r)[0]), "=r"((r)[1]), "=r"((r)[2]), "=r"((r)[3]) : "r"(addr))

#define LDSM4T(r, addr) \
    asm volatile("ldmatrix.sync.aligned.m8n8.x4.trans.shared.b16 {%0,%1,%2,%3}, [%4];" \
        : "=r"((r)[0]), "=r"((r)[1]), "=r"((r)[2]), "=r"((r)[3]) : "r"(addr))

// pack two f32 -> f16x2, first arg -> low half
__device__ __forceinline__ uint32_t packh(float lo, float hi) {
    uint32_t r;
    asm("cvt.rn.f16x2.f32 %0, %1, %2;" : "=r"(r) : "f"(hi), "f"(lo));
    return r;
}

#define CP16(dst, src) \
    asm volatile("cp.async.cg.shared.global [%0], [%1], 16;" :: "r"(dst), "l"(src))
#define CP_COMMIT() asm volatile("cp.async.commit_group;" ::: "memory")
#define CP_WAIT0()  asm volatile("cp.async.wait_group 0;" ::: "memory")

// ---------------------------------------------------------------------------
// SMEM layout (bytes). fp16 tiles: row stride 72 halves (144B, ldmatrix-safe)
// raw fp32 prefetch buffers: row stride 68 floats (272B)
// ---------------------------------------------------------------------------
#define KSTR 72
#define OFF_Q    0        // 128*72*2 = 18432 (staging only)
#define OFF_KH   18432    // 64*72*2 = 9216
#define OFF_VH   27648    // 9216
#define OFF_RAWK 36864    // 64*68*4 = 17408
#define OFF_RAWV 54272    // 17408
#define OFF_BIAS 71680    // 192 floats
#define SMEM_TOTAL 72448

// ---------------------------------------------------------------------------
// One CTA = 128 query rows of one (b,h); 8 warps, warp w owns rows 16w..16w+15.
// Pure fp16 operands (Q,K,V,P rounded once each), fp32 accumulate.
// cp.async double-buffer prefetch of next raw K/V tile.
// ---------------------------------------------------------------------------
__global__ void __launch_bounds__(256, 2)
attn_mma_kernel(const float* __restrict__ q, const float* __restrict__ k,
                const float* __restrict__ v,
                const int* __restrict__ event_length_i32,
                float* __restrict__ out) {
    extern __shared__ char smem[];
    const uint32_t sb = smem_u32(smem);

    const int tid = threadIdx.x;
    const int w   = tid >> 5;
    const int l   = tid & 31;
    const int qr  = l >> 2;          // 0..7
    const int qc2 = (l & 3) * 2;     // 0,2,4,6
    const int g   = l >> 3;          // ldmatrix lane group
    const int gr  = l & 7;

    const int b  = blockIdx.z;
    const int h  = blockIdx.y;
    const int i0 = blockIdx.x * BM;

    const long long base = ((long long)(b * NHEAD + h)) * S_LEN * DHEAD;
    const float* qh = q + base;
    const float* kh = k + base;
    const float* vh = v + base;
    float*       oh = out + base;

    const int L = (event_length_i32[1] == 0) ? event_length_i32[2 * b]
                                             : event_length_i32[b];
    const int jend = min(S_LEN, ((L + BN - 1) / BN) * BN);

    // --- stage Q (scaled by 1/8) fp16 into smem; prefetch tile 0 raw K/V ---
    #pragma unroll
    for (int it = 0; it < 8; it++) {
        int idx = tid + it * 256;       // 128 rows * 16 float4
        int row = idx >> 4;
        int c4  = (idx & 15) << 2;
        float4 t = *(const float4*)(qh + (i0 + row) * DHEAD + c4);
        uint32_t u0 = packh(t.x * 0.125f, t.y * 0.125f);
        uint32_t u1 = packh(t.z * 0.125f, t.w * 0.125f);
        *(uint2*)(smem + OFF_Q + (uint32_t)(row * KSTR + c4) * 2) = make_uint2(u0, u1);
    }
    #pragma unroll
    for (int it = 0; it < 4; it++) {
        int idx = tid + it * 256;       // 64 rows * 16 float4
        int row = idx >> 4;
        int c4  = (idx & 15) << 2;
        uint32_t roff = (uint32_t)(row * 68 + c4) * 4;
        CP16(sb + OFF_RAWK + roff, kh + row * DHEAD + c4);
        CP16(sb + OFF_RAWV + roff, vh + row * DHEAD + c4);
    }
    CP_COMMIT();
    __syncthreads();

    // --- hoist Q fragments into registers (tile-invariant) ---
    const int arow = 16 * w + ((g & 1) << 3) + gr;
    uint32_t qf[4][4];
    #pragma unroll
    for (int kk = 0; kk < 4; kk++) {
        int ad = 16 * kk + ((g >> 1) << 3);
        LDSM4(qf[kk], sb + OFF_Q + (uint32_t)(arow * KSTR + ad) * 2);
    }

    float oacc[32];
    #pragma unroll
    for (int i = 0; i < 32; i++) oacc[i] = 0.0f;
    float m0 = -1e30f, m1 = -1e30f, l0s = 0.0f, l1s = 0.0f;

    const float* biasrow = g_bias_delta + h * TBL + 2048;
    float* sB = (float*)(smem + OFF_BIAS);
    const int ri0 = 16 * w + qr;     // tile-local row of c0/c1

    for (int j0 = 0; j0 < jend; j0 += BN) {
        CP_WAIT0();
        __syncthreads();   // raw[j] visible; prev MMAs done with fp16 bufs

        // --- convert raw -> fp16 tiles; bias window ---
        #pragma unroll
        for (int it = 0; it < 4; it++) {
            int idx = tid + it * 256;
            int row = idx >> 4;
            int c4  = (idx & 15) << 2;
            uint32_t roff = (uint32_t)(row * 68 + c4) * 4;
            uint32_t soff = (uint32_t)(row * KSTR + c4) * 2;
            float4 t = *(const float4*)(smem + OFF_RAWK + roff);
            *(uint2*)(smem + OFF_KH + soff) =
                make_uint2(packh(t.x, t.y), packh(t.z, t.w));
            float4 u = *(const float4*)(smem + OFF_RAWV + roff);
            *(uint2*)(smem + OFF_VH + soff) =
                make_uint2(packh(u.x, u.y), packh(u.z, u.w));
        }
        if (tid < 191) {
            int di = (i0 - j0) + (tid - 63);
            di = min(2047, max(-2048, di));   // clamp (out-of-window entries unused)
            sB[tid] = biasrow[di];
        }
        __syncthreads();   // fp16 tiles + bias ready; raw buffer free

        // --- prefetch next tile raw K/V (overlaps MMAs below) ---
        if (j0 + BN < jend) {
            const float* kn = kh + (j0 + BN) * DHEAD;
            const float* vn = vh + (j0 + BN) * DHEAD;
            #pragma unroll
            for (int it = 0; it < 4; it++) {
                int idx = tid + it * 256;
                int row = idx >> 4;
                int c4  = (idx & 15) << 2;
                uint32_t roff = (uint32_t)(row * 68 + c4) * 4;
                CP16(sb + OFF_RAWK + roff, kn + row * DHEAD + c4);
                CP16(sb + OFF_RAWV + roff, vn + row * DHEAD + c4);
            }
        }
        CP_COMMIT();

        // --- S = q~ K~^T ---
        float sacc[32];
        #pragma unroll
        for (int i = 0; i < 32; i++) sacc[i] = 0.0f;

        #pragma unroll
        for (int kk = 0; kk < 4; kk++) {
            #pragma unroll
            for (int t2 = 0; t2 < 4; t2++) {
                int key = 16 * t2 + ((g >> 1) << 3) + gr;
                int d0  = 16 * kk + ((g & 1) << 3);
                uint32_t off = (uint32_t)(key * KSTR + d0) * 2;
                uint32_t kb[4];
                LDSM4(kb, sb + OFF_KH + off);
                float* dA = sacc + 8 * t2;
                float* dB = sacc + 8 * t2 + 4;
                MMAH(dA, qf[kk], kb[0], kb[1]);
                MMAH(dB, qf[kk], kb[2], kb[3]);
            }
        }

        // --- bias + key mask ---
        #pragma unroll
        for (int n = 0; n < 8; n++) {
            int cj = 8 * n + qc2;
            bool in0 = (j0 + cj)     < L;
            bool in1 = (j0 + cj + 1) < L;
            float b00 = sB[ri0 - cj + 63];
            float b01 = sB[ri0 - cj + 62];
            float b10 = sB[ri0 - cj + 71];
            float b11 = sB[ri0 - cj + 70];
            sacc[4 * n + 0] = in0 ? sacc[4 * n + 0] + b00 : -1e9f;
            sacc[4 * n + 1] = in1 ? sacc[4 * n + 1] + b01 : -1e9f;
            sacc[4 * n + 2] = in0 ? sacc[4 * n + 2] + b10 : -1e9f;
            sacc[4 * n + 3] = in1 ? sacc[4 * n + 3] + b11 : -1e9f;
        }

        // --- online softmax (rows live inside the warp quad) ---
        float mx0 = -1e30f, mx1 = -1e30f;
        #pragma unroll
        for (int n = 0; n < 8; n++) {
            mx0 = fmaxf(mx0, fmaxf(sacc[4 * n + 0], sacc[4 * n + 1]));
            mx1 = fmaxf(mx1, fmaxf(sacc[4 * n + 2], sacc[4 * n + 3]));
        }
        mx0 = fmaxf(mx0, __shfl_xor_sync(0xffffffffu, mx0, 1));
        mx0 = fmaxf(mx0, __shfl_xor_sync(0xffffffffu, mx0, 2));
        mx1 = fmaxf(mx1, __shfl_xor_sync(0xffffffffu, mx1, 1));
        mx1 = fmaxf(mx1, __shfl_xor_sync(0xffffffffu, mx1, 2));

        float mn0 = fmaxf(m0, mx0), mn1 = fmaxf(m1, mx1);
        float sc0 = __expf(m0 - mn0), sc1 = __expf(m1 - mn1);
        float rs0 = 0.0f, rs1 = 0.0f;
        #pragma unroll
        for (int n = 0; n < 8; n++) {
            sacc[4 * n + 0] = __expf(sacc[4 * n + 0] - mn0);
            sacc[4 * n + 1] = __expf(sacc[4 * n + 1] - mn0);
            sacc[4 * n + 2] = __expf(sacc[4 * n + 2] - mn1);
            sacc[4 * n + 3] = __expf(sacc[4 * n + 3] - mn1);
            rs0 += sacc[4 * n + 0] + sacc[4 * n + 1];
            rs1 += sacc[4 * n + 2] + sacc[4 * n + 3];
        }
        rs0 += __shfl_xor_sync(0xffffffffu, rs0, 1);
        rs0 += __shfl_xor_sync(0xffffffffu, rs0, 2);
        rs1 += __shfl_xor_sync(0xffffffffu, rs1, 1);
        rs1 += __shfl_xor_sync(0xffffffffu, rs1, 2);
        l0s = l0s * sc0 + rs0;  m0 = mn0;
        l1s = l1s * sc1 + rs1;  m1 = mn1;
        #pragma unroll
        for (int i = 0; i < 8; i++) {
            oacc[4 * i + 0] *= sc0;
            oacc[4 * i + 1] *= sc0;
            oacc[4 * i + 2] *= sc1;
            oacc[4 * i + 3] *= sc1;
        }

        // --- O += p~ V~ (P frags in registers) ---
        #pragma unroll
        for (int kk2 = 0; kk2 < 4; kk2++) {
            float* pa = sacc + 8 * kk2;
            uint32_t pf[4];
            pf[0] = packh(pa[0], pa[1]);
            pf[1] = packh(pa[2], pa[3]);
            pf[2] = packh(pa[4], pa[5]);
            pf[3] = packh(pa[6], pa[7]);

            int key = 16 * kk2 + ((g & 1) << 3) + gr;
            #pragma unroll
            for (int t2 = 0; t2 < 4; t2++) {
                int d0 = 16 * t2 + ((g >> 1) << 3);
                uint32_t off = (uint32_t)(key * KSTR + d0) * 2;
                uint32_t vb[4];
                LDSM4T(vb, sb + OFF_VH + off);
                float* oA = oacc + 8 * t2;
                float* oB = oacc + 8 * t2 + 4;
                MMAH(oA, pf, vb[0], vb[1]);
                MMAH(oB, pf, vb[2], vb[3]);
            }
        }
    }

    // --- epilogue: normalize and store ---
    float inv0 = 1.0f / l0s;
    float inv1 = 1.0f / l1s;
    int grow0 = i0 + ri0;
    int grow1 = grow0 + 8;
    #pragma unroll
    for (int n = 0; n < 8; n++) {
        *(float2*)(oh + grow0 * DHEAD + 8 * n + qc2) =
            make_float2(oacc[4 * n + 0] * inv0, oacc[4 * n + 1] * inv0);
        *(float2*)(oh + grow1 * DHEAD + 8 * n + qc2) =
            make_float2(oacc[4 * n + 2] * inv1, oacc[4 * n + 3] * inv1);
    }
}

// ---------------------------------------------------------------------------
extern "C" void kernel_launch(void* const* d_in, const int* in_sizes, int n_in,
                              void* d_out, int out_size) {
    const float* q          = (const float*)d_in[0];
    const float* k          = (const float*)d_in[1];
    const float* v          = (const float*)d_in[2];
    const float* bias_table = (const float*)d_in[3];
    const int*   event_len  = (const int*)d_in[4];
    float*       out        = (float*)d_out;

    (void)in_sizes; (void)n_in; (void)out_size;

    bias_init_kernel<<<(NHEAD * TBL + 255) / 256, 256>>>(bias_table);

    cudaFuncSetAttribute(attn_mma_kernel, cudaFuncAttributeMaxDynamicSharedMemorySize,
                         SMEM_TOTAL);

    dim3 grid(S_LEN / BM, NHEAD, NBATCH);
    attn_mma_kernel<<<grid, 256, SMEM_TOTAL>>>(q, k, v, event_len, out);
}

// round 9
// speedup vs baseline: 6.2120x; 1.1716x over previous
#include <cuda_runtime.h>
#include <cuda_fp16.h>
#include <cstdint>

// Problem constants
#define S_LEN  2048
#define DHEAD  64
#define NHEAD  16
#define NBATCH 2
#define BM     128
#define BN     64
#define TBL    4096
#define TOT    (NBATCH * NHEAD * S_LEN * DHEAD)   // 4,194,304

// ---------------------------------------------------------------------------
// Precomputed global state: bias per (head, i-j) [padded 64 each side],
// fp16 copies of q (pre-scaled), k, v.
// ---------------------------------------------------------------------------
__device__ float  g_bias[64 + NHEAD * TBL + 64];
__device__ __half g_q16[TOT];
__device__ __half g_k16[TOT];
__device__ __half g_v16[TOT];

__global__ void bias_init_kernel(const float* __restrict__ bias_table) {
    int idx = blockIdx.x * blockDim.x + threadIdx.x;
    if (idx >= NHEAD * TBL) return;
    int h = idx / TBL;
    int n = (idx % TBL) - 2048;  // n = i - j
    int bucket;
    if (n <= 0) {
        bucket = 0;
    } else if (n < 16) {
        bucket = n;
    } else {
        float vf = logf((float)n / 16.0f) / 2.7725887222397811f * 16.0f;
        vf = fminf(vf, 15.0f);
        bucket = 16 + (int)vf;
    }
    g_bias[64 + idx] = bias_table[bucket * NHEAD + h];
}

// pack two f32 -> f16x2, first arg -> low half
__device__ __forceinline__ uint32_t packh(float lo, float hi) {
    uint32_t r;
    asm("cvt.rn.f16x2.f32 %0, %1, %2;" : "=r"(r) : "f"(hi), "f"(lo));
    return r;
}

__global__ void cvt_kernel(const float* __restrict__ q,
                           const float* __restrict__ k,
                           const float* __restrict__ v) {
    int idx = blockIdx.x * blockDim.x + threadIdx.x;
    if (idx >= TOT / 4) return;
    float4 tq = ((const float4*)q)[idx];
    ((uint2*)g_q16)[idx] = make_uint2(packh(tq.x * 0.125f, tq.y * 0.125f),
                                      packh(tq.z * 0.125f, tq.w * 0.125f));
    float4 tk = ((const float4*)k)[idx];
    ((uint2*)g_k16)[idx] = make_uint2(packh(tk.x, tk.y), packh(tk.z, tk.w));
    float4 tv = ((const float4*)v)[idx];
    ((uint2*)g_v16)[idx] = make_uint2(packh(tv.x, tv.y), packh(tv.z, tv.w));
}

// ---------------------------------------------------------------------------
// PTX helpers (portable, plain sm_103 target)
// ---------------------------------------------------------------------------
__device__ __forceinline__ uint32_t smem_u32(const void* p) {
    uint32_t a;
    asm("{ .reg .u64 t; cvta.to.shared.u64 t, %1; cvt.u32.u64 %0, t; }" : "=r"(a) : "l"(p));
    return a;
}

#define MMAH(d, a, b0v, b1v) \
    asm volatile("mma.sync.aligned.m16n8k16.row.col.f32.f16.f16.f32 " \
        "{%0,%1,%2,%3}, {%4,%5,%6,%7}, {%8,%9}, {%0,%1,%2,%3};" \
        : "+f"((d)[0]), "+f"((d)[1]), "+f"((d)[2]), "+f"((d)[3]) \
        : "r"((a)[0]), "r"((a)[1]), "r"((a)[2]), "r"((a)[3]), "r"(b0v), "r"(b1v))

#define LDSM4(r, addr) \
    asm volatile("ldmatrix.sync.aligned.m8n8.x4.shared.b16 {%0,%1,%2,%3}, [%4];" \
        : "=r"((r)[0]), "=r"((r)[1]), "=r"((r)[2]), "=r"((r)[3]) : "r"(addr))

#define LDSM4T(r, addr) \
    asm volatile("ldmatrix.sync.aligned.m8n8.x4.trans.shared.b16 {%0,%1,%2,%3}, [%4];" \
        : "=r"((r)[0]), "=r"((r)[1]), "=r"((r)[2]), "=r"((r)[3]) : "r"(addr))

#define CP16(dst, src) \
    asm volatile("cp.async.cg.shared.global [%0], [%1], 16;" :: "r"(dst), "l"(src))
#define CP_COMMIT() asm volatile("cp.async.commit_group;" ::: "memory")
#define CP_WAIT0()  asm volatile("cp.async.wait_group 0;" ::: "memory")

// ---------------------------------------------------------------------------
// SMEM layout (bytes). fp16 tiles: row stride 72 halves (144B, ldmatrix-safe)
// Double-buffered K/V tiles and bias windows.
// ---------------------------------------------------------------------------
#define KSTR 72
#define OFF_Q   0        // 128*72*2 = 18432 (Q staging; frags hoisted)
#define OFF_K0  18432    // 64*72*2 = 9216 each
#define OFF_V0  27648
#define OFF_K1  36864
#define OFF_V1  46080
#define OFF_B0  55296    // 256 floats each
#define OFF_B1  56320
#define SMEM_TOTAL 57344

// ---------------------------------------------------------------------------
// One CTA = 128 query rows of one (b,h); 8 warps, warp w owns rows 16w..16w+15.
// fp16 operands pre-converted globally; per-tile: one barrier, double-buffered
// cp.async prefetch of next K/V fp16 tiles + bias window.
// ---------------------------------------------------------------------------
__global__ void __launch_bounds__(256, 2)
attn_mma_kernel(const int* __restrict__ event_length_i32,
                float* __restrict__ out) {
    extern __shared__ char smem[];
    const uint32_t sb = smem_u32(smem);

    const int tid = threadIdx.x;
    const int w   = tid >> 5;
    const int l   = tid & 31;
    const int qr  = l >> 2;          // 0..7
    const int qc2 = (l & 3) * 2;     // 0,2,4,6
    const int g   = l >> 3;          // ldmatrix lane group
    const int gr  = l & 7;

    const int b  = blockIdx.z;
    const int h  = blockIdx.y;
    const int i0 = blockIdx.x * BM;

    const long long base = ((long long)(b * NHEAD + h)) * S_LEN * DHEAD;
    const __half* q16 = g_q16 + base;
    const __half* k16 = g_k16 + base;
    const __half* v16 = g_v16 + base;
    float*        oh  = out + base;

    const int L = (event_length_i32[1] == 0) ? event_length_i32[2 * b]
                                             : event_length_i32[b];
    const int jend = min(S_LEN, ((L + BN - 1) / BN) * BN);

    const float* biasrow = g_bias + 64 + h * TBL + 2048;

    // --- prologue: async-copy Q, tile0 K/V, bias0 ---
    #pragma unroll
    for (int it = 0; it < 4; it++) {
        int c = tid + it * 256;          // 128 rows * 8 chunks
        int row = c >> 3, c16 = (c & 7) * 8;
        CP16(sb + OFF_Q + (uint32_t)(row * KSTR + c16) * 2,
             q16 + (i0 + row) * DHEAD + c16);
    }
    #pragma unroll
    for (int it = 0; it < 2; it++) {
        int c = tid + it * 256;          // 64 rows * 8 chunks
        int row = c >> 3, c16 = (c & 7) * 8;
        uint32_t soff = (uint32_t)(row * KSTR + c16) * 2;
        CP16(sb + OFF_K0 + soff, k16 + row * DHEAD + c16);
        CP16(sb + OFF_V0 + soff, v16 + row * DHEAD + c16);
    }
    if (tid < 64) CP16(sb + OFF_B0 + tid * 16, biasrow + i0 - 64 + tid * 4);
    CP_COMMIT();
    CP_WAIT0();
    __syncthreads();

    // --- hoist Q fragments into registers (tile-invariant) ---
    const int arow = 16 * w + ((g & 1) << 3) + gr;
    uint32_t qf[4][4];
    #pragma unroll
    for (int kk = 0; kk < 4; kk++) {
        int ad = 16 * kk + ((g >> 1) << 3);
        LDSM4(qf[kk], sb + OFF_Q + (uint32_t)(arow * KSTR + ad) * 2);
    }

    float oacc[32];
    #pragma unroll
    for (int i = 0; i < 32; i++) oacc[i] = 0.0f;
    float m0 = -1e30f, m1 = -1e30f, l0s = 0.0f, l1s = 0.0f;

    const int ri0 = 16 * w + qr;     // tile-local row of c0/c1

    int bufit = 0;
    for (int j0 = 0; j0 < jend; j0 += BN, bufit ^= 1) {
        const uint32_t offK = OFF_K0 + (uint32_t)bufit * 18432;
        const uint32_t offV = OFF_V0 + (uint32_t)bufit * 18432;
        const float*   sB   = (const float*)(smem + OFF_B0 + bufit * 1024);

        // --- prefetch next tile into the other buffers (overlaps compute) ---
        if (j0 + BN < jend) {
            const __half* kn = k16 + (j0 + BN) * DHEAD;
            const __half* vn = v16 + (j0 + BN) * DHEAD;
            uint32_t nK = OFF_K0 + (uint32_t)(bufit ^ 1) * 18432;
            uint32_t nV = OFF_V0 + (uint32_t)(bufit ^ 1) * 18432;
            #pragma unroll
            for (int it = 0; it < 2; it++) {
                int c = tid + it * 256;
                int row = c >> 3, c16 = (c & 7) * 8;
                uint32_t soff = (uint32_t)(row * KSTR + c16) * 2;
                CP16(sb + nK + soff, kn + row * DHEAD + c16);
                CP16(sb + nV + soff, vn + row * DHEAD + c16);
            }
            if (tid < 64)
                CP16(sb + OFF_B0 + (bufit ^ 1) * 1024 + tid * 16,
                     biasrow + (i0 - j0 - BN) - 64 + tid * 4);
        }
        CP_COMMIT();

        // --- S = q~ K~^T ---
        float sacc[32];
        #pragma unroll
        for (int i = 0; i < 32; i++) sacc[i] = 0.0f;

        #pragma unroll
        for (int kk = 0; kk < 4; kk++) {
            #pragma unroll
            for (int t2 = 0; t2 < 4; t2++) {
                int key = 16 * t2 + ((g >> 1) << 3) + gr;
                int d0  = 16 * kk + ((g & 1) << 3);
                uint32_t off = (uint32_t)(key * KSTR + d0) * 2;
                uint32_t kb[4];
                LDSM4(kb, sb + offK + off);
                float* dA = sacc + 8 * t2;
                float* dB = sacc + 8 * t2 + 4;
                MMAH(dA, qf[kk], kb[0], kb[1]);
                MMAH(dB, qf[kk], kb[2], kb[3]);
            }
        }

        // --- bias + key mask (window starts at (i0-j0)-64) ---
        #pragma unroll
        for (int n = 0; n < 8; n++) {
            int cj = 8 * n + qc2;
            bool in0 = (j0 + cj)     < L;
            bool in1 = (j0 + cj + 1) < L;
            float b00 = sB[ri0 - cj + 64];
            float b01 = sB[ri0 - cj + 63];
            float b10 = sB[ri0 - cj + 72];
            float b11 = sB[ri0 - cj + 71];
            sacc[4 * n + 0] = in0 ? sacc[4 * n + 0] + b00 : -1e9f;
            sacc[4 * n + 1] = in1 ? sacc[4 * n + 1] + b01 : -1e9f;
            sacc[4 * n + 2] = in0 ? sacc[4 * n + 2] + b10 : -1e9f;
            sacc[4 * n + 3] = in1 ? sacc[4 * n + 3] + b11 : -1e9f;
        }

        // --- online softmax (rows live inside the warp quad) ---
        float mx0 = -1e30f, mx1 = -1e30f;
        #pragma unroll
        for (int n = 0; n < 8; n++) {
            mx0 = fmaxf(mx0, fmaxf(sacc[4 * n + 0], sacc[4 * n + 1]));
            mx1 = fmaxf(mx1, fmaxf(sacc[4 * n + 2], sacc[4 * n + 3]));
        }
        mx0 = fmaxf(mx0, __shfl_xor_sync(0xffffffffu, mx0, 1));
        mx0 = fmaxf(mx0, __shfl_xor_sync(0xffffffffu, mx0, 2));
        mx1 = fmaxf(mx1, __shfl_xor_sync(0xffffffffu, mx1, 1));
        mx1 = fmaxf(mx1, __shfl_xor_sync(0xffffffffu, mx1, 2));

        float mn0 = fmaxf(m0, mx0), mn1 = fmaxf(m1, mx1);
        float sc0 = __expf(m0 - mn0), sc1 = __expf(m1 - mn1);
        float rs0 = 0.0f, rs1 = 0.0f;
        #pragma unroll
        for (int n = 0; n < 8; n++) {
            sacc[4 * n + 0] = __expf(sacc[4 * n + 0] - mn0);
            sacc[4 * n + 1] = __expf(sacc[4 * n + 1] - mn0);
            sacc[4 * n + 2] = __expf(sacc[4 * n + 2] - mn1);
            sacc[4 * n + 3] = __expf(sacc[4 * n + 3] - mn1);
            rs0 += sacc[4 * n + 0] + sacc[4 * n + 1];
            rs1 += sacc[4 * n + 2] + sacc[4 * n + 3];
        }
        rs0 += __shfl_xor_sync(0xffffffffu, rs0, 1);
        rs0 += __shfl_xor_sync(0xffffffffu, rs0, 2);
        rs1 += __shfl_xor_sync(0xffffffffu, rs1, 1);
        rs1 += __shfl_xor_sync(0xffffffffu, rs1, 2);
        l0s = l0s * sc0 + rs0;  m0 = mn0;
        l1s = l1s * sc1 + rs1;  m1 = mn1;
        #pragma unroll
        for (int i = 0; i < 8; i++) {
            oacc[4 * i + 0] *= sc0;
            oacc[4 * i + 1] *= sc0;
            oacc[4 * i + 2] *= sc1;
            oacc[4 * i + 3] *= sc1;
        }

        // --- O += p~ V~ (P frags in registers) ---
        #pragma unroll
        for (int kk2 = 0; kk2 < 4; kk2++) {
            float* pa = sacc + 8 * kk2;
            uint32_t pf[4];
            pf[0] = packh(pa[0], pa[1]);
            pf[1] = packh(pa[2], pa[3]);
            pf[2] = packh(pa[4], pa[5]);
            pf[3] = packh(pa[6], pa[7]);

            int key = 16 * kk2 + ((g & 1) << 3) + gr;
            #pragma unroll
            for (int t2 = 0; t2 < 4; t2++) {
                int d0 = 16 * t2 + ((g >> 1) << 3);
                uint32_t off = (uint32_t)(key * KSTR + d0) * 2;
                uint32_t vb[4];
                LDSM4T(vb, sb + offV + off);
                float* oA = oacc + 8 * t2;
                float* oB = oacc + 8 * t2 + 4;
                MMAH(oA, pf, vb[0], vb[1]);
                MMAH(oB, pf, vb[2], vb[3]);
            }
        }

        // --- make next tile resident & visible (single barrier per tile) ---
        CP_WAIT0();
        __syncthreads();
    }

    // --- epilogue: normalize and store ---
    float inv0 = 1.0f / l0s;
    float inv1 = 1.0f / l1s;
    int grow0 = i0 + ri0;
    int grow1 = grow0 + 8;
    #pragma unroll
    for (int n = 0; n < 8; n++) {
        *(float2*)(oh + grow0 * DHEAD + 8 * n + qc2) =
            make_float2(oacc[4 * n + 0] * inv0, oacc[4 * n + 1] * inv0);
        *(float2*)(oh + grow1 * DHEAD + 8 * n + qc2) =
            make_float2(oacc[4 * n + 2] * inv1, oacc[4 * n + 3] * inv1);
    }
}

// ---------------------------------------------------------------------------
extern "C" void kernel_launch(void* const* d_in, const int* in_sizes, int n_in,
                              void* d_out, int out_size) {
    const float* q          = (const float*)d_in[0];
    const float* k          = (const float*)d_in[1];
    const float* v          = (const float*)d_in[2];
    const float* bias_table = (const float*)d_in[3];
    const int*   event_len  = (const int*)d_in[4];
    float*       out        = (float*)d_out;

    (void)in_sizes; (void)n_in; (void)out_size;

    bias_init_kernel<<<(NHEAD * TBL + 255) / 256, 256>>>(bias_table);
    cvt_kernel<<<(TOT / 4 + 255) / 256, 256>>>(q, k, v);

    cudaFuncSetAttribute(attn_mma_kernel, cudaFuncAttributeMaxDynamicSharedMemorySize,
                         SMEM_TOTAL);

    dim3 grid(S_LEN / BM, NHEAD, NBATCH);
    attn_mma_kernel<<<grid, 256, SMEM_TOTAL>>>(event_len, out);
}

// round 10
// speedup vs baseline: 7.0868x; 1.1408x over previous
#include <cuda_runtime.h>
#include <cuda_fp16.h>
#include <cstdint>

// Problem constants
#define S_LEN  2048
#define DHEAD  64
#define NHEAD  16
#define NBATCH 2
#define BM     128
#define BN     64
#define TBL    4096
#define TOT    (NBATCH * NHEAD * S_LEN * DHEAD)   // 4,194,304

#define LOG2E      1.4426950408889634f
#define QSCALE     0.18033688011119373f   // 0.125 * log2(e)

// ---------------------------------------------------------------------------
// Global precomputed state: bias (log2-scaled, padded) + fp16 K/V copies
// ---------------------------------------------------------------------------
__device__ float  g_bias[64 + NHEAD * TBL + 256];
__device__ __half g_k16[TOT];
__device__ __half g_v16[TOT];

// pack two f32 -> f16x2, first arg -> low half
__device__ __forceinline__ uint32_t packh(float lo, float hi) {
    uint32_t r;
    asm("cvt.rn.f16x2.f32 %0, %1, %2;" : "=r"(r) : "f"(hi), "f"(lo));
    return r;
}

// Merged preprocess: K/V fp32->fp16 + bias table (log2e-scaled)
__global__ void prep_kernel(const float* __restrict__ k,
                            const float* __restrict__ v,
                            const float* __restrict__ bias_table) {
    int idx = blockIdx.x * blockDim.x + threadIdx.x;
    if (idx < NHEAD * TBL) {
        int h = idx / TBL;
        int n = (idx % TBL) - 2048;  // n = i - j
        int bucket;
        if (n <= 0) {
            bucket = 0;
        } else if (n < 16) {
            bucket = n;
        } else {
            float vf = logf((float)n / 16.0f) / 2.7725887222397811f * 16.0f;
            vf = fminf(vf, 15.0f);
            bucket = 16 + (int)vf;
        }
        g_bias[64 + idx] = bias_table[bucket * NHEAD + h] * LOG2E;
    }
    if (idx < TOT / 4) {
        float4 tk = ((const float4*)k)[idx];
        ((uint2*)g_k16)[idx] = make_uint2(packh(tk.x, tk.y), packh(tk.z, tk.w));
        float4 tv = ((const float4*)v)[idx];
        ((uint2*)g_v16)[idx] = make_uint2(packh(tv.x, tv.y), packh(tv.z, tv.w));
    }
}

// ---------------------------------------------------------------------------
// PTX helpers (portable, plain sm_103 target)
// ---------------------------------------------------------------------------
__device__ __forceinline__ uint32_t smem_u32(const void* p) {
    uint32_t a;
    asm("{ .reg .u64 t; cvta.to.shared.u64 t, %1; cvt.u32.u64 %0, t; }" : "=r"(a) : "l"(p));
    return a;
}
__device__ __forceinline__ float ex2(float x) {
    float y;
    asm("ex2.approx.ftz.f32 %0, %1;" : "=f"(y) : "f"(x));
    return y;
}

#define MMAH(d, a, b0v, b1v) \
    asm volatile("mma.sync.aligned.m16n8k16.row.col.f32.f16.f16.f32 " \
        "{%0,%1,%2,%3}, {%4,%5,%6,%7}, {%8,%9}, {%0,%1,%2,%3};" \
        : "+f"((d)[0]), "+f"((d)[1]), "+f"((d)[2]), "+f"((d)[3]) \
        : "r"((a)[0]), "r"((a)[1]), "r"((a)[2]), "r"((a)[3]), "r"(b0v), "r"(b1v))

#define LDSM4(r, addr) \
    asm volatile("ldmatrix.sync.aligned.m8n8.x4.shared.b16 {%0,%1,%2,%3}, [%4];" \
        : "=r"((r)[0]), "=r"((r)[1]), "=r"((r)[2]), "=r"((r)[3]) : "r"(addr))

#define LDSM4T(r, addr) \
    asm volatile("ldmatrix.sync.aligned.m8n8.x4.trans.shared.b16 {%0,%1,%2,%3}, [%4];" \
        : "=r"((r)[0]), "=r"((r)[1]), "=r"((r)[2]), "=r"((r)[3]) : "r"(addr))

#define CP16(dst, src) \
    asm volatile("cp.async.cg.shared.global [%0], [%1], 16;" :: "r"(dst), "l"(src))
#define CP_COMMIT() asm volatile("cp.async.commit_group;" ::: "memory")
#define CP_WAIT0()  asm volatile("cp.async.wait_group 0;" ::: "memory")

// ---------------------------------------------------------------------------
// SMEM layout (bytes). fp16 tiles: row stride 72 halves (144B, ldmatrix-safe)
// ---------------------------------------------------------------------------
#define KSTR 72
#define OFF_Q   0        // 128*72*2 = 18432 (Q staging; frags hoisted)
#define OFF_K0  18432    // 64*72*2 = 9216 each
#define OFF_V0  27648
#define OFF_K1  36864
#define OFF_V1  46080
#define OFF_B0  55296    // 256 floats each
#define OFF_B1  56320
#define SMEM_TOTAL 57344

// ---------------------------------------------------------------------------
// One CTA = 128 query rows of one (b,h); 8 warps, warp w owns rows 16w..16w+15.
// ---------------------------------------------------------------------------
__global__ void __launch_bounds__(256, 2)
attn_mma_kernel(const float* __restrict__ q,
                const int* __restrict__ event_length_i32,
                float* __restrict__ out) {
    extern __shared__ char smem[];
    const uint32_t sb = smem_u32(smem);

    const int tid = threadIdx.x;
    const int w   = tid >> 5;
    const int l   = tid & 31;
    const int qr  = l >> 2;          // 0..7
    const int qc2 = (l & 3) * 2;     // 0,2,4,6
    const int g   = l >> 3;          // ldmatrix lane group
    const int gr  = l & 7;

    const int b  = blockIdx.z;
    const int h  = blockIdx.y;
    const int i0 = blockIdx.x * BM;

    const long long base = ((long long)(b * NHEAD + h)) * S_LEN * DHEAD;
    const float*  qh  = q + base;
    const __half* k16 = g_k16 + base;
    const __half* v16 = g_v16 + base;
    float*        oh  = out + base;

    const int L = (event_length_i32[1] == 0) ? event_length_i32[2 * b]
                                             : event_length_i32[b];
    const int jend = min(S_LEN, ((L + BN - 1) / BN) * BN);

    const float* biasrow = g_bias + 64 + h * TBL + 2048;

    // --- prologue: async-copy tile0 K/V + bias0; LDG-convert Q (overlaps) ---
    #pragma unroll
    for (int it = 0; it < 2; it++) {
        int c = tid + it * 256;          // 64 rows * 8 chunks
        int row = c >> 3, c16 = (c & 7) * 8;
        uint32_t soff = (uint32_t)(row * KSTR + c16) * 2;
        CP16(sb + OFF_K0 + soff, k16 + row * DHEAD + c16);
        CP16(sb + OFF_V0 + soff, v16 + row * DHEAD + c16);
    }
    if (tid < 64) CP16(sb + OFF_B0 + tid * 16, biasrow + i0 - 64 + tid * 4);
    CP_COMMIT();

    #pragma unroll
    for (int it = 0; it < 8; it++) {
        int idx = tid + it * 256;        // 128 rows * 16 float4
        int row = idx >> 4;
        int c4  = (idx & 15) << 2;
        float4 t = *(const float4*)(qh + (i0 + row) * DHEAD + c4);
        uint32_t u0 = packh(t.x * QSCALE, t.y * QSCALE);
        uint32_t u1 = packh(t.z * QSCALE, t.w * QSCALE);
        *(uint2*)(smem + OFF_Q + (uint32_t)(row * KSTR + c4) * 2) = make_uint2(u0, u1);
    }
    CP_WAIT0();
    __syncthreads();

    // --- hoist Q fragments into registers (tile-invariant) ---
    const int arow = 16 * w + ((g & 1) << 3) + gr;
    uint32_t qf[4][4];
    #pragma unroll
    for (int kk = 0; kk < 4; kk++) {
        int ad = 16 * kk + ((g >> 1) << 3);
        LDSM4(qf[kk], sb + OFF_Q + (uint32_t)(arow * KSTR + ad) * 2);
    }

    float oacc[32];
    #pragma unroll
    for (int i = 0; i < 32; i++) oacc[i] = 0.0f;
    float m0 = -1e30f, m1 = -1e30f, l0s = 0.0f, l1s = 0.0f;

    const int ri0 = 16 * w + qr;     // tile-local row of c0/c1

    int bufit = 0;
    for (int j0 = 0; j0 < jend; j0 += BN, bufit ^= 1) {
        const uint32_t offK = OFF_K0 + (uint32_t)bufit * 18432;
        const uint32_t offV = OFF_V0 + (uint32_t)bufit * 18432;
        const float*   sB   = (const float*)(smem + OFF_B0 + bufit * 1024);

        // --- prefetch next tile into the other buffers (overlaps compute) ---
        if (j0 + BN < jend) {
            const __half* kn = k16 + (j0 + BN) * DHEAD;
            const __half* vn = v16 + (j0 + BN) * DHEAD;
            uint32_t nK = OFF_K0 + (uint32_t)(bufit ^ 1) * 18432;
            uint32_t nV = OFF_V0 + (uint32_t)(bufit ^ 1) * 18432;
            #pragma unroll
            for (int it = 0; it < 2; it++) {
                int c = tid + it * 256;
                int row = c >> 3, c16 = (c & 7) * 8;
                uint32_t soff = (uint32_t)(row * KSTR + c16) * 2;
                CP16(sb + nK + soff, kn + row * DHEAD + c16);
                CP16(sb + nV + soff, vn + row * DHEAD + c16);
            }
            if (tid < 64)
                CP16(sb + OFF_B0 + (bufit ^ 1) * 1024 + tid * 16,
                     biasrow + (i0 - j0 - BN) - 64 + tid * 4);
        }
        CP_COMMIT();

        // --- S = q~ K~^T (log2-scaled) ---
        float sacc[32];
        #pragma unroll
        for (int i = 0; i < 32; i++) sacc[i] = 0.0f;

        #pragma unroll
        for (int kk = 0; kk < 4; kk++) {
            #pragma unroll
            for (int t2 = 0; t2 < 4; t2++) {
                int key = 16 * t2 + ((g >> 1) << 3) + gr;
                int d0  = 16 * kk + ((g & 1) << 3);
                uint32_t off = (uint32_t)(key * KSTR + d0) * 2;
                uint32_t kb[4];
                LDSM4(kb, sb + offK + off);
                float* dA = sacc + 8 * t2;
                float* dB = sacc + 8 * t2 + 4;
                MMAH(dA, qf[kk], kb[0], kb[1]);
                MMAH(dB, qf[kk], kb[2], kb[3]);
            }
        }

        // --- bias + key mask (window starts at (i0-j0)-64) ---
        #pragma unroll
        for (int n = 0; n < 8; n++) {
            int cj = 8 * n + qc2;
            bool in0 = (j0 + cj)     < L;
            bool in1 = (j0 + cj + 1) < L;
            float b00 = sB[ri0 - cj + 64];
            float b01 = sB[ri0 - cj + 63];
            float b10 = sB[ri0 - cj + 72];
            float b11 = sB[ri0 - cj + 71];
            sacc[4 * n + 0] = in0 ? sacc[4 * n + 0] + b00 : -1e9f;
            sacc[4 * n + 1] = in1 ? sacc[4 * n + 1] + b01 : -1e9f;
            sacc[4 * n + 2] = in0 ? sacc[4 * n + 2] + b10 : -1e9f;
            sacc[4 * n + 3] = in1 ? sacc[4 * n + 3] + b11 : -1e9f;
        }

        // --- online softmax in log2 domain ---
        float mx0 = -1e30f, mx1 = -1e30f;
        #pragma unroll
        for (int n = 0; n < 8; n++) {
            mx0 = fmaxf(mx0, fmaxf(sacc[4 * n + 0], sacc[4 * n + 1]));
            mx1 = fmaxf(mx1, fmaxf(sacc[4 * n + 2], sacc[4 * n + 3]));
        }
        mx0 = fmaxf(mx0, __shfl_xor_sync(0xffffffffu, mx0, 1));
        mx0 = fmaxf(mx0, __shfl_xor_sync(0xffffffffu, mx0, 2));
        mx1 = fmaxf(mx1, __shfl_xor_sync(0xffffffffu, mx1, 1));
        mx1 = fmaxf(mx1, __shfl_xor_sync(0xffffffffu, mx1, 2));

        float mn0 = fmaxf(m0, mx0), mn1 = fmaxf(m1, mx1);
        float sc0 = ex2(m0 - mn0), sc1 = ex2(m1 - mn1);
        float rs0 = 0.0f, rs1 = 0.0f;
        #pragma unroll
        for (int n = 0; n < 8; n++) {
            sacc[4 * n + 0] = ex2(sacc[4 * n + 0] - mn0);
            sacc[4 * n + 1] = ex2(sacc[4 * n + 1] - mn0);
            sacc[4 * n + 2] = ex2(sacc[4 * n + 2] - mn1);
            sacc[4 * n + 3] = ex2(sacc[4 * n + 3] - mn1);
            rs0 += sacc[4 * n + 0] + sacc[4 * n + 1];
            rs1 += sacc[4 * n + 2] + sacc[4 * n + 3];
        }
        rs0 += __shfl_xor_sync(0xffffffffu, rs0, 1);
        rs0 += __shfl_xor_sync(0xffffffffu, rs0, 2);
        rs1 += __shfl_xor_sync(0xffffffffu, rs1, 1);
        rs1 += __shfl_xor_sync(0xffffffffu, rs1, 2);
        l0s = l0s * sc0 + rs0;  m0 = mn0;
        l1s = l1s * sc1 + rs1;  m1 = mn1;
        #pragma unroll
        for (int i = 0; i < 8; i++) {
            oacc[4 * i + 0] *= sc0;
            oacc[4 * i + 1] *= sc0;
            oacc[4 * i + 2] *= sc1;
            oacc[4 * i + 3] *= sc1;
        }

        // --- build ALL P fragments first, then uninterrupted MMA stream ---
        uint32_t pf[4][4];
        #pragma unroll
        for (int kk2 = 0; kk2 < 4; kk2++) {
            float* pa = sacc + 8 * kk2;
            pf[kk2][0] = packh(pa[0], pa[1]);
            pf[kk2][1] = packh(pa[2], pa[3]);
            pf[kk2][2] = packh(pa[4], pa[5]);
            pf[kk2][3] = packh(pa[6], pa[7]);
        }
        #pragma unroll
        for (int kk2 = 0; kk2 < 4; kk2++) {
            int key = 16 * kk2 + ((g & 1) << 3) + gr;
            #pragma unroll
            for (int t2 = 0; t2 < 4; t2++) {
                int d0 = 16 * t2 + ((g >> 1) << 3);
                uint32_t off = (uint32_t)(key * KSTR + d0) * 2;
                uint32_t vb[4];
                LDSM4T(vb, sb + offV + off);
                float* oA = oacc + 8 * t2;
                float* oB = oacc + 8 * t2 + 4;
                MMAH(oA, pf[kk2], vb[0], vb[1]);
                MMAH(oB, pf[kk2], vb[2], vb[3]);
            }
        }

        // --- make next tile resident & visible (single barrier per tile) ---
        CP_WAIT0();
        __syncthreads();
    }

    // --- epilogue: normalize and store ---
    float inv0 = 1.0f / l0s;
    float inv1 = 1.0f / l1s;
    int grow0 = i0 + ri0;
    int grow1 = grow0 + 8;
    #pragma unroll
    for (int n = 0; n < 8; n++) {
        *(float2*)(oh + grow0 * DHEAD + 8 * n + qc2) =
            make_float2(oacc[4 * n + 0] * inv0, oacc[4 * n + 1] * inv0);
        *(float2*)(oh + grow1 * DHEAD + 8 * n + qc2) =
            make_float2(oacc[4 * n + 2] * inv1, oacc[4 * n + 3] * inv1);
    }
}

// ---------------------------------------------------------------------------
extern "C" void kernel_launch(void* const* d_in, const int* in_sizes, int n_in,
                              void* d_out, int out_size) {
    const float* q          = (const float*)d_in[0];
    const float* k          = (const float*)d_in[1];
    const float* v          = (const float*)d_in[2];
    const float* bias_table = (const float*)d_in[3];
    const int*   event_len  = (const int*)d_in[4];
    float*       out        = (float*)d_out;

    (void)in_sizes; (void)n_in; (void)out_size;

    prep_kernel<<<(TOT / 4 + 255) / 256, 256>>>(k, v, bias_table);

    cudaFuncSetAttribute(attn_mma_kernel, cudaFuncAttributeMaxDynamicSharedMemorySize,
                         SMEM_TOTAL);

    dim3 grid(S_LEN / BM, NHEAD, NBATCH);
    attn_mma_kernel<<<grid, 256, SMEM_TOTAL>>>(q, event_len, out);
}

// round 11
// speedup vs baseline: 7.5233x; 1.0616x over previous
#include <cuda_runtime.h>
#include <cuda_fp16.h>
#include <cstdint>

// Problem constants
#define S_LEN  2048
#define DHEAD  64
#define NHEAD  16
#define NBATCH 2
#define BM     128
#define BN     64
#define TBL    4096
#define TOT    (NBATCH * NHEAD * S_LEN * DHEAD)   // 4,194,304

#define LOG2E      1.4426950408889634f
#define QSCALE     0.18033688011119373f   // 0.125 * log2(e)

// ---------------------------------------------------------------------------
// Global precomputed state: bias (log2-scaled, padded) + fp16 K/V copies
// ---------------------------------------------------------------------------
__device__ float  g_bias[64 + NHEAD * TBL + 256];
__device__ __half g_k16[TOT];
__device__ __half g_v16[TOT];

// pack two f32 -> f16x2, first arg -> low half
__device__ __forceinline__ uint32_t packh(float lo, float hi) {
    uint32_t r;
    asm("cvt.rn.f16x2.f32 %0, %1, %2;" : "=r"(r) : "f"(hi), "f"(lo));
    return r;
}

// Merged preprocess: K/V fp32->fp16 + bias table (log2e-scaled)
__global__ void prep_kernel(const float* __restrict__ k,
                            const float* __restrict__ v,
                            const float* __restrict__ bias_table) {
    int idx = blockIdx.x * blockDim.x + threadIdx.x;
    if (idx < NHEAD * TBL) {
        int h = idx / TBL;
        int n = (idx % TBL) - 2048;  // n = i - j
        int bucket;
        if (n <= 0) {
            bucket = 0;
        } else if (n < 16) {
            bucket = n;
        } else {
            float vf = logf((float)n / 16.0f) / 2.7725887222397811f * 16.0f;
            vf = fminf(vf, 15.0f);
            bucket = 16 + (int)vf;
        }
        g_bias[64 + idx] = bias_table[bucket * NHEAD + h] * LOG2E;
    }
    if (idx < TOT / 4) {
        float4 tk = ((const float4*)k)[idx];
        ((uint2*)g_k16)[idx] = make_uint2(packh(tk.x, tk.y), packh(tk.z, tk.w));
        float4 tv = ((const float4*)v)[idx];
        ((uint2*)g_v16)[idx] = make_uint2(packh(tv.x, tv.y), packh(tv.z, tv.w));
    }
}

// ---------------------------------------------------------------------------
// PTX helpers (portable, plain sm_103 target)
// ---------------------------------------------------------------------------
__device__ __forceinline__ uint32_t smem_u32(const void* p) {
    uint32_t a;
    asm("{ .reg .u64 t; cvta.to.shared.u64 t, %1; cvt.u32.u64 %0, t; }" : "=r"(a) : "l"(p));
    return a;
}
__device__ __forceinline__ float ex2(float x) {
    float y;
    asm("ex2.approx.ftz.f32 %0, %1;" : "=f"(y) : "f"(x));
    return y;
}

#define MMAH(d, a, b0v, b1v) \
    asm volatile("mma.sync.aligned.m16n8k16.row.col.f32.f16.f16.f32 " \
        "{%0,%1,%2,%3}, {%4,%5,%6,%7}, {%8,%9}, {%0,%1,%2,%3};" \
        : "+f"((d)[0]), "+f"((d)[1]), "+f"((d)[2]), "+f"((d)[3]) \
        : "r"((a)[0]), "r"((a)[1]), "r"((a)[2]), "r"((a)[3]), "r"(b0v), "r"(b1v))

#define LDSM4(r, addr) \
    asm volatile("ldmatrix.sync.aligned.m8n8.x4.shared.b16 {%0,%1,%2,%3}, [%4];" \
        : "=r"((r)[0]), "=r"((r)[1]), "=r"((r)[2]), "=r"((r)[3]) : "r"(addr))

#define LDSM4T(r, addr) \
    asm volatile("ldmatrix.sync.aligned.m8n8.x4.trans.shared.b16 {%0,%1,%2,%3}, [%4];" \
        : "=r"((r)[0]), "=r"((r)[1]), "=r"((r)[2]), "=r"((r)[3]) : "r"(addr))

#define CP16(dst, src) \
    asm volatile("cp.async.cg.shared.global [%0], [%1], 16;" :: "r"(dst), "l"(src))
#define CP_COMMIT() asm volatile("cp.async.commit_group;" ::: "memory")
#define CP_WAIT0()  asm volatile("cp.async.wait_group 0;" ::: "memory")

// ---------------------------------------------------------------------------
// SMEM layout (bytes). fp16 tiles: row stride 72 halves (144B, ldmatrix-safe)
// ---------------------------------------------------------------------------
#define KSTR 72
#define OFF_Q   0        // 128*72*2 = 18432 (Q staging; frags hoisted)
#define OFF_K0  18432    // 64*72*2 = 9216 each
#define OFF_V0  27648
#define OFF_K1  36864
#define OFF_V1  46080
#define OFF_B0  55296    // 256 floats each
#define OFF_B1  56320
#define SMEM_TOTAL 57344

// ---------------------------------------------------------------------------
// One CTA = 128 query rows of one (b,h); 4 warps, warp w owns rows 32w..32w+31
// (two m16 A-fragments). Each K/V ldmatrix feeds 4 MMAs (2 row-frags).
// ---------------------------------------------------------------------------
__global__ void __launch_bounds__(128, 2)
attn_mma_kernel(const float* __restrict__ q,
                const int* __restrict__ event_length_i32,
                float* __restrict__ out) {
    extern __shared__ char smem[];
    const uint32_t sb = smem_u32(smem);

    const int tid = threadIdx.x;
    const int w   = tid >> 5;
    const int l   = tid & 31;
    const int qr  = l >> 2;          // 0..7
    const int qc2 = (l & 3) * 2;     // 0,2,4,6
    const int g   = l >> 3;          // ldmatrix lane group
    const int gr  = l & 7;

    const int b  = blockIdx.z;
    const int h  = blockIdx.y;
    const int i0 = blockIdx.x * BM;

    const long long base = ((long long)(b * NHEAD + h)) * S_LEN * DHEAD;
    const float*  qh  = q + base;
    const __half* k16 = g_k16 + base;
    const __half* v16 = g_v16 + base;
    float*        oh  = out + base;

    const int L = (event_length_i32[1] == 0) ? event_length_i32[2 * b]
                                             : event_length_i32[b];
    const int jend = min(S_LEN, ((L + BN - 1) / BN) * BN);

    const float* biasrow = g_bias + 64 + h * TBL + 2048;

    // --- prologue: async-copy tile0 K/V + bias0; LDG-convert Q (overlaps) ---
    #pragma unroll
    for (int it = 0; it < 4; it++) {
        int c = tid + it * 128;          // 64 rows * 8 chunks
        int row = c >> 3, c16 = (c & 7) * 8;
        uint32_t soff = (uint32_t)(row * KSTR + c16) * 2;
        CP16(sb + OFF_K0 + soff, k16 + row * DHEAD + c16);
        CP16(sb + OFF_V0 + soff, v16 + row * DHEAD + c16);
    }
    if (tid < 64) CP16(sb + OFF_B0 + tid * 16, biasrow + i0 - 64 + tid * 4);
    CP_COMMIT();

    #pragma unroll
    for (int it = 0; it < 16; it++) {
        int idx = tid + it * 128;        // 128 rows * 16 float4
        int row = idx >> 4;
        int c4  = (idx & 15) << 2;
        float4 t = *(const float4*)(qh + (i0 + row) * DHEAD + c4);
        uint32_t u0 = packh(t.x * QSCALE, t.y * QSCALE);
        uint32_t u1 = packh(t.z * QSCALE, t.w * QSCALE);
        *(uint2*)(smem + OFF_Q + (uint32_t)(row * KSTR + c4) * 2) = make_uint2(u0, u1);
    }
    CP_WAIT0();
    __syncthreads();

    // --- hoist Q fragments (two row-frags per warp, tile-invariant) ---
    const int arow = 32 * w + ((g & 1) << 3) + gr;
    uint32_t qf[2][4][4];
    #pragma unroll
    for (int r = 0; r < 2; r++) {
        #pragma unroll
        for (int kk = 0; kk < 4; kk++) {
            int ad = 16 * kk + ((g >> 1) << 3);
            LDSM4(qf[r][kk],
                  sb + OFF_Q + (uint32_t)((arow + 16 * r) * KSTR + ad) * 2);
        }
    }

    float oacc[2][32];
    #pragma unroll
    for (int r = 0; r < 2; r++)
        #pragma unroll
        for (int i = 0; i < 32; i++) oacc[r][i] = 0.0f;
    float mrun[4], lrun[4];
    #pragma unroll
    for (int i = 0; i < 4; i++) { mrun[i] = -1e30f; lrun[i] = 0.0f; }

    const int ri0 = 32 * w + qr;     // tile-local row (frag r adds 16r, +8 for d2/d3)

    int bufit = 0;
    for (int j0 = 0; j0 < jend; j0 += BN, bufit ^= 1) {
        const uint32_t offK = OFF_K0 + (uint32_t)bufit * 18432;
        const uint32_t offV = OFF_V0 + (uint32_t)bufit * 18432;
        const float*   sB   = (const float*)(smem + OFF_B0 + bufit * 1024);

        // --- prefetch next tile into the other buffers (overlaps compute) ---
        if (j0 + BN < jend) {
            const __half* kn = k16 + (j0 + BN) * DHEAD;
            const __half* vn = v16 + (j0 + BN) * DHEAD;
            uint32_t nK = OFF_K0 + (uint32_t)(bufit ^ 1) * 18432;
            uint32_t nV = OFF_V0 + (uint32_t)(bufit ^ 1) * 18432;
            #pragma unroll
            for (int it = 0; it < 4; it++) {
                int c = tid + it * 128;
                int row = c >> 3, c16 = (c & 7) * 8;
                uint32_t soff = (uint32_t)(row * KSTR + c16) * 2;
                CP16(sb + nK + soff, kn + row * DHEAD + c16);
                CP16(sb + nV + soff, vn + row * DHEAD + c16);
            }
            if (tid < 64)
                CP16(sb + OFF_B0 + (bufit ^ 1) * 1024 + tid * 16,
                     biasrow + (i0 - j0 - BN) - 64 + tid * 4);
        }
        CP_COMMIT();

        // --- S = q~ K~^T (each K ldmatrix feeds both row-frags) ---
        float sacc[2][32];
        #pragma unroll
        for (int r = 0; r < 2; r++)
            #pragma unroll
            for (int i = 0; i < 32; i++) sacc[r][i] = 0.0f;

        #pragma unroll
        for (int kk = 0; kk < 4; kk++) {
            #pragma unroll
            for (int t2 = 0; t2 < 4; t2++) {
                int key = 16 * t2 + ((g >> 1) << 3) + gr;
                int d0  = 16 * kk + ((g & 1) << 3);
                uint32_t off = (uint32_t)(key * KSTR + d0) * 2;
                uint32_t kb[4];
                LDSM4(kb, sb + offK + off);
                #pragma unroll
                for (int r = 0; r < 2; r++) {
                    float* dA = sacc[r] + 8 * t2;
                    float* dB = sacc[r] + 8 * t2 + 4;
                    MMAH(dA, qf[r][kk], kb[0], kb[1]);
                    MMAH(dB, qf[r][kk], kb[2], kb[3]);
                }
            }
        }

        // --- bias + key mask + online softmax (4 row groups) ---
        #pragma unroll
        for (int r = 0; r < 2; r++) {
            int rA = ri0 + 16 * r;       // rows rA (d0,d1) and rA+8 (d2,d3)
            #pragma unroll
            for (int n = 0; n < 8; n++) {
                int cj = 8 * n + qc2;
                bool in0 = (j0 + cj)     < L;
                bool in1 = (j0 + cj + 1) < L;
                float b00 = sB[rA - cj + 64];
                float b01 = sB[rA - cj + 63];
                float b10 = sB[rA - cj + 72];
                float b11 = sB[rA - cj + 71];
                sacc[r][4 * n + 0] = in0 ? sacc[r][4 * n + 0] + b00 : -1e9f;
                sacc[r][4 * n + 1] = in1 ? sacc[r][4 * n + 1] + b01 : -1e9f;
                sacc[r][4 * n + 2] = in0 ? sacc[r][4 * n + 2] + b10 : -1e9f;
                sacc[r][4 * n + 3] = in1 ? sacc[r][4 * n + 3] + b11 : -1e9f;
            }

            float mx0 = -1e30f, mx1 = -1e30f;
            #pragma unroll
            for (int n = 0; n < 8; n++) {
                mx0 = fmaxf(mx0, fmaxf(sacc[r][4 * n + 0], sacc[r][4 * n + 1]));
                mx1 = fmaxf(mx1, fmaxf(sacc[r][4 * n + 2], sacc[r][4 * n + 3]));
            }
            mx0 = fmaxf(mx0, __shfl_xor_sync(0xffffffffu, mx0, 1));
            mx0 = fmaxf(mx0, __shfl_xor_sync(0xffffffffu, mx0, 2));
            mx1 = fmaxf(mx1, __shfl_xor_sync(0xffffffffu, mx1, 1));
            mx1 = fmaxf(mx1, __shfl_xor_sync(0xffffffffu, mx1, 2));

            float mn0 = fmaxf(mrun[2 * r], mx0), mn1 = fmaxf(mrun[2 * r + 1], mx1);
            float sc0 = ex2(mrun[2 * r] - mn0), sc1 = ex2(mrun[2 * r + 1] - mn1);
            float rs0 = 0.0f, rs1 = 0.0f;
            #pragma unroll
            for (int n = 0; n < 8; n++) {
                sacc[r][4 * n + 0] = ex2(sacc[r][4 * n + 0] - mn0);
                sacc[r][4 * n + 1] = ex2(sacc[r][4 * n + 1] - mn0);
                sacc[r][4 * n + 2] = ex2(sacc[r][4 * n + 2] - mn1);
                sacc[r][4 * n + 3] = ex2(sacc[r][4 * n + 3] - mn1);
                rs0 += sacc[r][4 * n + 0] + sacc[r][4 * n + 1];
                rs1 += sacc[r][4 * n + 2] + sacc[r][4 * n + 3];
            }
            rs0 += __shfl_xor_sync(0xffffffffu, rs0, 1);
            rs0 += __shfl_xor_sync(0xffffffffu, rs0, 2);
            rs1 += __shfl_xor_sync(0xffffffffu, rs1, 1);
            rs1 += __shfl_xor_sync(0xffffffffu, rs1, 2);
            lrun[2 * r]     = lrun[2 * r]     * sc0 + rs0;  mrun[2 * r]     = mn0;
            lrun[2 * r + 1] = lrun[2 * r + 1] * sc1 + rs1;  mrun[2 * r + 1] = mn1;
            #pragma unroll
            for (int i = 0; i < 8; i++) {
                oacc[r][4 * i + 0] *= sc0;
                oacc[r][4 * i + 1] *= sc0;
                oacc[r][4 * i + 2] *= sc1;
                oacc[r][4 * i + 3] *= sc1;
            }
        }

        // --- build ALL P fragments, then uninterrupted MMA stream ---
        uint32_t pf[2][4][4];
        #pragma unroll
        for (int r = 0; r < 2; r++) {
            #pragma unroll
            for (int kk2 = 0; kk2 < 4; kk2++) {
                float* pa = sacc[r] + 8 * kk2;
                pf[r][kk2][0] = packh(pa[0], pa[1]);
                pf[r][kk2][1] = packh(pa[2], pa[3]);
                pf[r][kk2][2] = packh(pa[4], pa[5]);
                pf[r][kk2][3] = packh(pa[6], pa[7]);
            }
        }
        #pragma unroll
        for (int kk2 = 0; kk2 < 4; kk2++) {
            int key = 16 * kk2 + ((g & 1) << 3) + gr;
            #pragma unroll
            for (int t2 = 0; t2 < 4; t2++) {
                int d0 = 16 * t2 + ((g >> 1) << 3);
                uint32_t off = (uint32_t)(key * KSTR + d0) * 2;
                uint32_t vb[4];
                LDSM4T(vb, sb + offV + off);
                #pragma unroll
                for (int r = 0; r < 2; r++) {
                    float* oA = oacc[r] + 8 * t2;
                    float* oB = oacc[r] + 8 * t2 + 4;
                    MMAH(oA, pf[r][kk2], vb[0], vb[1]);
                    MMAH(oB, pf[r][kk2], vb[2], vb[3]);
                }
            }
        }

        // --- make next tile resident & visible (single barrier per tile) ---
        CP_WAIT0();
        __syncthreads();
    }

    // --- epilogue: normalize and store (4 row groups) ---
    #pragma unroll
    for (int r = 0; r < 2; r++) {
        float inv0 = 1.0f / lrun[2 * r];
        float inv1 = 1.0f / lrun[2 * r + 1];
        int grow0 = i0 + ri0 + 16 * r;
        int grow1 = grow0 + 8;
        #pragma unroll
        for (int n = 0; n < 8; n++) {
            *(float2*)(oh + grow0 * DHEAD + 8 * n + qc2) =
                make_float2(oacc[r][4 * n + 0] * inv0, oacc[r][4 * n + 1] * inv0);
            *(float2*)(oh + grow1 * DHEAD + 8 * n + qc2) =
                make_float2(oacc[r][4 * n + 2] * inv1, oacc[r][4 * n + 3] * inv1);
        }
    }
}

// ---------------------------------------------------------------------------
extern "C" void kernel_launch(void* const* d_in, const int* in_sizes, int n_in,
                              void* d_out, int out_size) {
    const float* q          = (const float*)d_in[0];
    const float* k          = (const float*)d_in[1];
    const float* v          = (const float*)d_in[2];
    const float* bias_table = (const float*)d_in[3];
    const int*   event_len  = (const int*)d_in[4];
    float*       out        = (float*)d_out;

    (void)in_sizes; (void)n_in; (void)out_size;

    prep_kernel<<<(TOT / 4 + 255) / 256, 256>>>(k, v, bias_table);

    cudaFuncSetAttribute(attn_mma_kernel, cudaFuncAttributeMaxDynamicSharedMemorySize,
                         SMEM_TOTAL);

    dim3 grid(S_LEN / BM, NHEAD, NBATCH);
    attn_mma_kernel<<<grid, 128, SMEM_TOTAL>>>(q, event_len, out);
}

// round 13
// speedup vs baseline: 7.7230x; 1.0265x over previous
#include <cuda_runtime.h>
#include <cuda_fp16.h>
#include <cstdint>

// Problem constants
#define S_LEN  2048
#define DHEAD  64
#define NHEAD  16
#define NBATCH 2
#define BM     128
#define BN     64
#define TBL    4096
#define TOT    (NBATCH * NHEAD * S_LEN * DHEAD)   // 4,194,304

#define LOG2E      1.4426950408889634f
#define QSCALE     0.18033688011119373f   // 0.125 * log2(e)

// ---------------------------------------------------------------------------
// Global precomputed state: bias (log2-scaled, padded) + fp16 K/V copies
// ---------------------------------------------------------------------------
__device__ float  g_bias[64 + NHEAD * TBL + 256];
__device__ __half g_k16[TOT];
__device__ __half g_v16[TOT];

// pack two f32 -> f16x2, first arg -> low half
__device__ __forceinline__ uint32_t packh(float lo, float hi) {
    uint32_t r;
    asm("cvt.rn.f16x2.f32 %0, %1, %2;" : "=r"(r) : "f"(hi), "f"(lo));
    return r;
}

// Merged preprocess: K/V fp32->fp16 + bias table (log2e-scaled)
__global__ void prep_kernel(const float* __restrict__ k,
                            const float* __restrict__ v,
                            const float* __restrict__ bias_table) {
    int idx = blockIdx.x * blockDim.x + threadIdx.x;
    if (idx < NHEAD * TBL) {
        int h = idx / TBL;
        int n = (idx % TBL) - 2048;  // n = i - j
        int bucket;
        if (n <= 0) {
            bucket = 0;
        } else if (n < 16) {
            bucket = n;
        } else {
            float vf = logf((float)n / 16.0f) / 2.7725887222397811f * 16.0f;
            vf = fminf(vf, 15.0f);
            bucket = 16 + (int)vf;
        }
        g_bias[64 + idx] = bias_table[bucket * NHEAD + h] * LOG2E;
    }
    if (idx < TOT / 4) {
        float4 tk = ((const float4*)k)[idx];
        ((uint2*)g_k16)[idx] = make_uint2(packh(tk.x, tk.y), packh(tk.z, tk.w));
        float4 tv = ((const float4*)v)[idx];
        ((uint2*)g_v16)[idx] = make_uint2(packh(tv.x, tv.y), packh(tv.z, tv.w));
    }
}

// ---------------------------------------------------------------------------
// PTX helpers (portable, plain sm_103 target)
// ---------------------------------------------------------------------------
__device__ __forceinline__ uint32_t smem_u32(const void* p) {
    uint32_t a;
    asm("{ .reg .u64 t; cvta.to.shared.u64 t, %1; cvt.u32.u64 %0, t; }" : "=r"(a) : "l"(p));
    return a;
}
__device__ __forceinline__ float ex2(float x) {
    float y;
    asm("ex2.approx.ftz.f32 %0, %1;" : "=f"(y) : "f"(x));
    return y;
}

#define MMAH(d, a, b0v, b1v) \
    asm volatile("mma.sync.aligned.m16n8k16.row.col.f32.f16.f16.f32 " \
        "{%0,%1,%2,%3}, {%4,%5,%6,%7}, {%8,%9}, {%0,%1,%2,%3};" \
        : "+f"((d)[0]), "+f"((d)[1]), "+f"((d)[2]), "+f"((d)[3]) \
        : "r"((a)[0]), "r"((a)[1]), "r"((a)[2]), "r"((a)[3]), "r"(b0v), "r"(b1v))

#define LDSM4(r, addr) \
    asm volatile("ldmatrix.sync.aligned.m8n8.x4.shared.b16 {%0,%1,%2,%3}, [%4];" \
        : "=r"((r)[0]), "=r"((r)[1]), "=r"((r)[2]), "=r"((r)[3]) : "r"(addr))

#define LDSM4T(r, addr) \
    asm volatile("ldmatrix.sync.aligned.m8n8.x4.trans.shared.b16 {%0,%1,%2,%3}, [%4];" \
        : "=r"((r)[0]), "=r"((r)[1]), "=r"((r)[2]), "=r"((r)[3]) : "r"(addr))

#define CP16(dst, src) \
    asm volatile("cp.async.cg.shared.global [%0], [%1], 16;" :: "r"(dst), "l"(src))
#define CP_COMMIT() asm volatile("cp.async.commit_group;" ::: "memory")
#define CP_WAIT0()  asm volatile("cp.async.wait_group 0;" ::: "memory")

// ---------------------------------------------------------------------------
// SMEM layout (bytes). fp16 tiles: row stride 72 halves (144B, ldmatrix-safe)
// ---------------------------------------------------------------------------
#define KSTR 72
#define OFF_Q   0        // 128*72*2 = 18432 (Q staging; frags hoisted)
#define OFF_K0  18432    // 64*72*2 = 9216 each
#define OFF_V0  27648
#define OFF_K1  36864
#define OFF_V1  46080
#define OFF_B0  55296    // 256 floats each
#define OFF_B1  56320
#define SMEM_TOTAL 57344

// ---------------------------------------------------------------------------
// One CTA = 128 query rows of one (b,h); 4 warps, warp w owns rows 32w..32w+31.
// Lazy-rescale online softmax: exponent frame mO updated only on warp-vote
// (gap > 12 -> fp16 P still far from overflow); l kept as per-thread partial.
// ---------------------------------------------------------------------------
__global__ void __launch_bounds__(128, 2)
attn_mma_kernel(const float* __restrict__ q,
                const int* __restrict__ event_length_i32,
                float* __restrict__ out) {
    extern __shared__ char smem[];
    const uint32_t sb = smem_u32(smem);

    const int tid = threadIdx.x;
    const int w   = tid >> 5;
    const int l   = tid & 31;
    const int qr  = l >> 2;          // 0..7
    const int qc2 = (l & 3) * 2;     // 0,2,4,6
    const int g   = l >> 3;          // ldmatrix lane group
    const int gr  = l & 7;

    const int b  = blockIdx.z;
    const int h  = blockIdx.y;
    const int i0 = blockIdx.x * BM;

    const long long base = ((long long)(b * NHEAD + h)) * S_LEN * DHEAD;
    const float*  qh  = q + base;
    const __half* k16 = g_k16 + base;
    const __half* v16 = g_v16 + base;
    float*        oh  = out + base;

    const int L = (event_length_i32[1] == 0) ? event_length_i32[2 * b]
                                             : event_length_i32[b];
    const int jend = min(S_LEN, ((L + BN - 1) / BN) * BN);

    const float* biasrow = g_bias + 64 + h * TBL + 2048;

    // --- prologue: async-copy tile0 K/V + bias0; LDG-convert Q (overlaps) ---
    #pragma unroll
    for (int it = 0; it < 4; it++) {
        int c = tid + it * 128;          // 64 rows * 8 chunks
        int row = c >> 3, c16 = (c & 7) * 8;
        uint32_t soff = (uint32_t)(row * KSTR + c16) * 2;
        CP16(sb + OFF_K0 + soff, k16 + row * DHEAD + c16);
        CP16(sb + OFF_V0 + soff, v16 + row * DHEAD + c16);
    }
    if (tid < 64) CP16(sb + OFF_B0 + tid * 16, biasrow + i0 - 64 + tid * 4);
    CP_COMMIT();

    #pragma unroll
    for (int it = 0; it < 16; it++) {
        int idx = tid + it * 128;        // 128 rows * 16 float4
        int row = idx >> 4;
        int c4  = (idx & 15) << 2;
        float4 t = *(const float4*)(qh + (i0 + row) * DHEAD + c4);
        uint32_t u0 = packh(t.x * QSCALE, t.y * QSCALE);
        uint32_t u1 = packh(t.z * QSCALE, t.w * QSCALE);
        *(uint2*)(smem + OFF_Q + (uint32_t)(row * KSTR + c4) * 2) = make_uint2(u0, u1);
    }
    CP_WAIT0();
    __syncthreads();

    // --- hoist Q fragments (two row-frags per warp, tile-invariant) ---
    const int arow = 32 * w + ((g & 1) << 3) + gr;
    uint32_t qf[2][4][4];
    #pragma unroll
    for (int r = 0; r < 2; r++) {
        #pragma unroll
        for (int kk = 0; kk < 4; kk++) {
            int ad = 16 * kk + ((g >> 1) << 3);
            LDSM4(qf[r][kk],
                  sb + OFF_Q + (uint32_t)((arow + 16 * r) * KSTR + ad) * 2);
        }
    }

    float oacc[2][32];
    #pragma unroll
    for (int r = 0; r < 2; r++)
        #pragma unroll
        for (int i = 0; i < 32; i++) oacc[r][i] = 0.0f;
    // exponent frame + per-thread partial row-sum, per row-group
    float mO[4], lp[4];
    #pragma unroll
    for (int i = 0; i < 4; i++) { mO[i] = -1e30f; lp[i] = 0.0f; }

    const int ri0 = 32 * w + qr;     // tile-local row (frag r adds 16r, +8 for d2/d3)

    int bufit = 0;
    for (int j0 = 0; j0 < jend; j0 += BN, bufit ^= 1) {
        const uint32_t offK = OFF_K0 + (uint32_t)bufit * 18432;
        const uint32_t offV = OFF_V0 + (uint32_t)bufit * 18432;
        const float*   sB   = (const float*)(smem + OFF_B0 + bufit * 1024);

        // --- prefetch next tile into the other buffers (overlaps compute) ---
        if (j0 + BN < jend) {
            const __half* kn = k16 + (j0 + BN) * DHEAD;
            const __half* vn = v16 + (j0 + BN) * DHEAD;
            uint32_t nK = OFF_K0 + (uint32_t)(bufit ^ 1) * 18432;
            uint32_t nV = OFF_V0 + (uint32_t)(bufit ^ 1) * 18432;
            #pragma unroll
            for (int it = 0; it < 4; it++) {
                int c = tid + it * 128;
                int row = c >> 3, c16 = (c & 7) * 8;
                uint32_t soff = (uint32_t)(row * KSTR + c16) * 2;
                CP16(sb + nK + soff, kn + row * DHEAD + c16);
                CP16(sb + nV + soff, vn + row * DHEAD + c16);
            }
            if (tid < 64)
                CP16(sb + OFF_B0 + (bufit ^ 1) * 1024 + tid * 16,
                     biasrow + (i0 - j0 - BN) - 64 + tid * 4);
        }
        CP_COMMIT();

        // --- S = q~ K~^T (each K ldmatrix feeds both row-frags) ---
        float sacc[2][32];
        #pragma unroll
        for (int r = 0; r < 2; r++)
            #pragma unroll
            for (int i = 0; i < 32; i++) sacc[r][i] = 0.0f;

        #pragma unroll
        for (int kk = 0; kk < 4; kk++) {
            #pragma unroll
            for (int t2 = 0; t2 < 4; t2++) {
                int key = 16 * t2 + ((g >> 1) << 3) + gr;
                int d0  = 16 * kk + ((g & 1) << 3);
                uint32_t off = (uint32_t)(key * KSTR + d0) * 2;
                uint32_t kb[4];
                LDSM4(kb, sb + offK + off);
                #pragma unroll
                for (int r = 0; r < 2; r++) {
                    float* dA = sacc[r] + 8 * t2;
                    float* dB = sacc[r] + 8 * t2 + 4;
                    MMAH(dA, qf[r][kk], kb[0], kb[1]);
                    MMAH(dB, qf[r][kk], kb[2], kb[3]);
                }
            }
        }

        // --- bias + key mask ---
        #pragma unroll
        for (int r = 0; r < 2; r++) {
            int rA = ri0 + 16 * r;
            #pragma unroll
            for (int n = 0; n < 8; n++) {
                int cj = 8 * n + qc2;
                bool in0 = (j0 + cj)     < L;
                bool in1 = (j0 + cj + 1) < L;
                float b00 = sB[rA - cj + 64];
                float b01 = sB[rA - cj + 63];
                float b10 = sB[rA - cj + 72];
                float b11 = sB[rA - cj + 71];
                sacc[r][4 * n + 0] = in0 ? sacc[r][4 * n + 0] + b00 : -1e9f;
                sacc[r][4 * n + 1] = in1 ? sacc[r][4 * n + 1] + b01 : -1e9f;
                sacc[r][4 * n + 2] = in0 ? sacc[r][4 * n + 2] + b10 : -1e9f;
                sacc[r][4 * n + 3] = in1 ? sacc[r][4 * n + 3] + b11 : -1e9f;
            }
        }

        // --- lazy frame check: local maxes + one warp vote ---
        float lm[4];
        #pragma unroll
        for (int r = 0; r < 2; r++) {
            float a0 = -1e30f, a1 = -1e30f;
            #pragma unroll
            for (int n = 0; n < 8; n++) {
                a0 = fmaxf(a0, fmaxf(sacc[r][4 * n + 0], sacc[r][4 * n + 1]));
                a1 = fmaxf(a1, fmaxf(sacc[r][4 * n + 2], sacc[r][4 * n + 3]));
            }
            lm[2 * r] = a0; lm[2 * r + 1] = a1;
        }
        bool need = (lm[0] > mO[0] + 12.0f) || (lm[1] > mO[1] + 12.0f) ||
                    (lm[2] > mO[2] + 12.0f) || (lm[3] > mO[3] + 12.0f);
        if (__any_sync(0xffffffffu, need)) {
            // rare path: full max reduction + rescale O, l into new frame
            #pragma unroll
            for (int g4 = 0; g4 < 4; g4++) {
                float mx = lm[g4];
                mx = fmaxf(mx, __shfl_xor_sync(0xffffffffu, mx, 1));
                mx = fmaxf(mx, __shfl_xor_sync(0xffffffffu, mx, 2));
                float mn = fmaxf(mO[g4], mx);
                float sc = ex2(mO[g4] - mn);
                lp[g4] *= sc;
                mO[g4] = mn;
                float* oa = oacc[g4 >> 1] + ((g4 & 1) ? 2 : 0);
                #pragma unroll
                for (int i = 0; i < 8; i++) {
                    oa[4 * i + 0] *= sc;
                    oa[4 * i + 1] *= sc;
                }
            }
        }

        // --- exp in stale frame + per-thread partial sums (no shfl!) ---
        #pragma unroll
        for (int r = 0; r < 2; r++) {
            float s0 = 0.0f, s1 = 0.0f;
            #pragma unroll
            for (int n = 0; n < 8; n++) {
                sacc[r][4 * n + 0] = ex2(sacc[r][4 * n + 0] - mO[2 * r]);
                sacc[r][4 * n + 1] = ex2(sacc[r][4 * n + 1] - mO[2 * r]);
                sacc[r][4 * n + 2] = ex2(sacc[r][4 * n + 2] - mO[2 * r + 1]);
                sacc[r][4 * n + 3] = ex2(sacc[r][4 * n + 3] - mO[2 * r + 1]);
                s0 += sacc[r][4 * n + 0] + sacc[r][4 * n + 1];
                s1 += sacc[r][4 * n + 2] + sacc[r][4 * n + 3];
            }
            lp[2 * r]     += s0;
            lp[2 * r + 1] += s1;
        }

        // --- build ALL P fragments, then uninterrupted MMA stream ---
        uint32_t pf[2][4][4];
        #pragma unroll
        for (int r = 0; r < 2; r++) {
            #pragma unroll
            for (int kk2 = 0; kk2 < 4; kk2++) {
                float* pa = sacc[r] + 8 * kk2;
                pf[r][kk2][0] = packh(pa[0], pa[1]);
                pf[r][kk2][1] = packh(pa[2], pa[3]);
                pf[r][kk2][2] = packh(pa[4], pa[5]);
                pf[r][kk2][3] = packh(pa[6], pa[7]);
            }
        }
        #pragma unroll
        for (int kk2 = 0; kk2 < 4; kk2++) {
            int key = 16 * kk2 + ((g & 1) << 3) + gr;
            #pragma unroll
            for (int t2 = 0; t2 < 4; t2++) {
                int d0 = 16 * t2 + ((g >> 1) << 3);
                uint32_t off = (uint32_t)(key * KSTR + d0) * 2;
                uint32_t vb[4];
                LDSM4T(vb, sb + offV + off);
                #pragma unroll
                for (int r = 0; r < 2; r++) {
                    float* oA = oacc[r] + 8 * t2;
                    float* oB = oacc[r] + 8 * t2 + 4;
                    MMAH(oA, pf[r][kk2], vb[0], vb[1]);
                    MMAH(oB, pf[r][kk2], vb[2], vb[3]);
                }
            }
        }

        // --- make next tile resident & visible (single barrier per tile) ---
        CP_WAIT0();
        __syncthreads();
    }

    // --- epilogue: reduce l across quad, normalize, store ---
    float inv[4];
    #pragma unroll
    for (int g4 = 0; g4 < 4; g4++) {
        float s = lp[g4];
        s += __shfl_xor_sync(0xffffffffu, s, 1);
        s += __shfl_xor_sync(0xffffffffu, s, 2);
        inv[g4] = 1.0f / s;
    }
    #pragma unroll
    for (int r = 0; r < 2; r++) {
        int grow0 = i0 + ri0 + 16 * r;
        int grow1 = grow0 + 8;
        #pragma unroll
        for (int n = 0; n < 8; n++) {
            *(float2*)(oh + grow0 * DHEAD + 8 * n + qc2) =
                make_float2(oacc[r][4 * n + 0] * inv[2 * r],
                            oacc[r][4 * n + 1] * inv[2 * r]);
            *(float2*)(oh + grow1 * DHEAD + 8 * n + qc2) =
                make_float2(oacc[r][4 * n + 2] * inv[2 * r + 1],
                            oacc[r][4 * n + 3] * inv[2 * r + 1]);
        }
    }
}

// ---------------------------------------------------------------------------
extern "C" void kernel_launch(void* const* d_in, const int* in_sizes, int n_in,
                              void* d_out, int out_size) {
    const float* q          = (const float*)d_in[0];
    const float* k          = (const float*)d_in[1];
    const float* v          = (const float*)d_in[2];
    const float* bias_table = (const float*)d_in[3];
    const int*   event_len  = (const int*)d_in[4];
    float*       out        = (float*)d_out;

    (void)in_sizes; (void)n_in; (void)out_size;

    prep_kernel<<<(TOT / 4 + 255) / 256, 256>>>(k, v, bias_table);

    cudaFuncSetAttribute(attn_mma_kernel, cudaFuncAttributeMaxDynamicSharedMemorySize,
                         SMEM_TOTAL);

    dim3 grid(S_LEN / BM, NHEAD, NBATCH);
    attn_mma_kernel<<<grid, 128, SMEM_TOTAL>>>(q, event_len, out);
}

// round 14
// speedup vs baseline: 8.2357x; 1.0664x over previous
#include <cuda_runtime.h>
#include <cuda_fp16.h>
#include <cstdint>

// Problem constants
#define S_LEN  2048
#define DHEAD  64
#define NHEAD  16
#define NBATCH 2
#define BM     128
#define BN     64
#define TBL    4096
#define TOT    (NBATCH * NHEAD * S_LEN * DHEAD)   // 4,194,304

#define LOG2E      1.4426950408889634f
#define QSCALE     0.18033688011119373f   // 0.125 * log2(e)

// ---------------------------------------------------------------------------
// Global precomputed state: bias (log2-scaled, padded) + fp16 K/V copies
// ---------------------------------------------------------------------------
__device__ float  g_bias[64 + NHEAD * TBL + 256];
__device__ __half g_k16[TOT];
__device__ __half g_v16[TOT];

// pack two f32 -> f16x2, first arg -> low half
__device__ __forceinline__ uint32_t packh(float lo, float hi) {
    uint32_t r;
    asm("cvt.rn.f16x2.f32 %0, %1, %2;" : "=r"(r) : "f"(hi), "f"(lo));
    return r;
}

// Merged preprocess: K/V fp32->fp16 + bias table (log2e-scaled)
__global__ void prep_kernel(const float* __restrict__ k,
                            const float* __restrict__ v,
                            const float* __restrict__ bias_table) {
    int idx = blockIdx.x * blockDim.x + threadIdx.x;
    if (idx < NHEAD * TBL) {
        int h = idx / TBL;
        int n = (idx % TBL) - 2048;  // n = i - j
        int bucket;
        if (n <= 0) {
            bucket = 0;
        } else if (n < 16) {
            bucket = n;
        } else {
            float vf = logf((float)n / 16.0f) / 2.7725887222397811f * 16.0f;
            vf = fminf(vf, 15.0f);
            bucket = 16 + (int)vf;
        }
        g_bias[64 + idx] = bias_table[bucket * NHEAD + h] * LOG2E;
    }
    if (idx < TOT / 4) {
        float4 tk = ((const float4*)k)[idx];
        ((uint2*)g_k16)[idx] = make_uint2(packh(tk.x, tk.y), packh(tk.z, tk.w));
        float4 tv = ((const float4*)v)[idx];
        ((uint2*)g_v16)[idx] = make_uint2(packh(tv.x, tv.y), packh(tv.z, tv.w));
    }
}

// ---------------------------------------------------------------------------
// PTX helpers (portable, plain sm_103 target)
// ---------------------------------------------------------------------------
__device__ __forceinline__ uint32_t smem_u32(const void* p) {
    uint32_t a;
    asm("{ .reg .u64 t; cvta.to.shared.u64 t, %1; cvt.u32.u64 %0, t; }" : "=r"(a) : "l"(p));
    return a;
}
__device__ __forceinline__ float ex2(float x) {
    float y;
    asm("ex2.approx.ftz.f32 %0, %1;" : "=f"(y) : "f"(x));
    return y;
}
// fused: pack (x,y) to f16x2 then 2^() both halves in one MUFU op
__device__ __forceinline__ uint32_t h2ex2(float x, float y) {
    uint32_t t = packh(x, y);
    uint32_t r;
    asm("ex2.approx.f16x2 %0, %1;" : "=r"(r) : "r"(t));
    return r;
}
__device__ __forceinline__ uint32_t hadd2u(uint32_t a, uint32_t b) {
    uint32_t r;
    asm("add.rn.f16x2 %0, %1, %2;" : "=r"(r) : "r"(a), "r"(b));
    return r;
}
__device__ __forceinline__ float2 h22f2(uint32_t p) {
    __half2 h = *(__half2*)&p;
    return __half22float2(h);
}

#define MMAH(d, a, b0v, b1v) \
    asm volatile("mma.sync.aligned.m16n8k16.row.col.f32.f16.f16.f32 " \
        "{%0,%1,%2,%3}, {%4,%5,%6,%7}, {%8,%9}, {%0,%1,%2,%3};" \
        : "+f"((d)[0]), "+f"((d)[1]), "+f"((d)[2]), "+f"((d)[3]) \
        : "r"((a)[0]), "r"((a)[1]), "r"((a)[2]), "r"((a)[3]), "r"(b0v), "r"(b1v))

#define LDSM4(r, addr) \
    asm volatile("ldmatrix.sync.aligned.m8n8.x4.shared.b16 {%0,%1,%2,%3}, [%4];" \
        : "=r"((r)[0]), "=r"((r)[1]), "=r"((r)[2]), "=r"((r)[3]) : "r"(addr))

#define LDSM4T(r, addr) \
    asm volatile("ldmatrix.sync.aligned.m8n8.x4.trans.shared.b16 {%0,%1,%2,%3}, [%4];" \
        : "=r"((r)[0]), "=r"((r)[1]), "=r"((r)[2]), "=r"((r)[3]) : "r"(addr))

#define CP16(dst, src) \
    asm volatile("cp.async.cg.shared.global [%0], [%1], 16;" :: "r"(dst), "l"(src))
#define CP_COMMIT() asm volatile("cp.async.commit_group;" ::: "memory")
#define CP_WAIT0()  asm volatile("cp.async.wait_group 0;" ::: "memory")

// ---------------------------------------------------------------------------
// SMEM layout (bytes). fp16 tiles: row stride 72 halves (144B, ldmatrix-safe)
// ---------------------------------------------------------------------------
#define KSTR 72
#define OFF_Q   0        // 128*72*2 = 18432 (Q staging; frags hoisted)
#define OFF_K0  18432    // 64*72*2 = 9216 each
#define OFF_V0  27648
#define OFF_K1  36864
#define OFF_V1  46080
#define OFF_B0  55296    // 256 floats each
#define OFF_B1  56320
#define SMEM_TOTAL 57344

// ---------------------------------------------------------------------------
// One CTA = 128 query rows of one (b,h); 4 warps, warp w owns rows 32w..32w+31.
// Lazy-rescale frame (vote threshold 10 -> P <= 2^10, fp16-safe sums).
// exp computed in f16x2 directly into P fragments.
// ---------------------------------------------------------------------------
__global__ void __launch_bounds__(128, 2)
attn_mma_kernel(const float* __restrict__ q,
                const int* __restrict__ event_length_i32,
                float* __restrict__ out) {
    extern __shared__ char smem[];
    const uint32_t sb = smem_u32(smem);

    const int tid = threadIdx.x;
    const int w   = tid >> 5;
    const int l   = tid & 31;
    const int qr  = l >> 2;          // 0..7
    const int qc2 = (l & 3) * 2;     // 0,2,4,6
    const int g   = l >> 3;          // ldmatrix lane group
    const int gr  = l & 7;

    const int b  = blockIdx.z;
    const int h  = blockIdx.y;
    const int i0 = blockIdx.x * BM;

    const long long base = ((long long)(b * NHEAD + h)) * S_LEN * DHEAD;
    const float*  qh  = q + base;
    const __half* k16 = g_k16 + base;
    const __half* v16 = g_v16 + base;
    float*        oh  = out + base;

    const int L = (event_length_i32[1] == 0) ? event_length_i32[2 * b]
                                             : event_length_i32[b];
    const int jend = min(S_LEN, ((L + BN - 1) / BN) * BN);

    const float* biasrow = g_bias + 64 + h * TBL + 2048;

    // --- prologue: async-copy tile0 K/V + bias0; LDG-convert Q (overlaps) ---
    #pragma unroll
    for (int it = 0; it < 4; it++) {
        int c = tid + it * 128;          // 64 rows * 8 chunks
        int row = c >> 3, c16 = (c & 7) * 8;
        uint32_t soff = (uint32_t)(row * KSTR + c16) * 2;
        CP16(sb + OFF_K0 + soff, k16 + row * DHEAD + c16);
        CP16(sb + OFF_V0 + soff, v16 + row * DHEAD + c16);
    }
    if (tid < 64) CP16(sb + OFF_B0 + tid * 16, biasrow + i0 - 64 + tid * 4);
    CP_COMMIT();

    #pragma unroll
    for (int it = 0; it < 16; it++) {
        int idx = tid + it * 128;        // 128 rows * 16 float4
        int row = idx >> 4;
        int c4  = (idx & 15) << 2;
        float4 t = *(const float4*)(qh + (i0 + row) * DHEAD + c4);
        uint32_t u0 = packh(t.x * QSCALE, t.y * QSCALE);
        uint32_t u1 = packh(t.z * QSCALE, t.w * QSCALE);
        *(uint2*)(smem + OFF_Q + (uint32_t)(row * KSTR + c4) * 2) = make_uint2(u0, u1);
    }
    CP_WAIT0();
    __syncthreads();

    // --- hoist Q fragments (two row-frags per warp, tile-invariant) ---
    const int arow = 32 * w + ((g & 1) << 3) + gr;
    uint32_t qf[2][4][4];
    #pragma unroll
    for (int r = 0; r < 2; r++) {
        #pragma unroll
        for (int kk = 0; kk < 4; kk++) {
            int ad = 16 * kk + ((g >> 1) << 3);
            LDSM4(qf[r][kk],
                  sb + OFF_Q + (uint32_t)((arow + 16 * r) * KSTR + ad) * 2);
        }
    }

    float oacc[2][32];
    #pragma unroll
    for (int r = 0; r < 2; r++)
        #pragma unroll
        for (int i = 0; i < 32; i++) oacc[r][i] = 0.0f;
    float mO[4], lp[4];
    #pragma unroll
    for (int i = 0; i < 4; i++) { mO[i] = -1e30f; lp[i] = 0.0f; }

    const int ri0 = 32 * w + qr;     // tile-local row (frag r adds 16r, +8 for d2/d3)

    int bufit = 0;
    for (int j0 = 0; j0 < jend; j0 += BN, bufit ^= 1) {
        const uint32_t offK = OFF_K0 + (uint32_t)bufit * 18432;
        const uint32_t offV = OFF_V0 + (uint32_t)bufit * 18432;
        const float*   sB   = (const float*)(smem + OFF_B0 + bufit * 1024);

        // --- prefetch next tile into the other buffers (overlaps compute) ---
        if (j0 + BN < jend) {
            const __half* kn = k16 + (j0 + BN) * DHEAD;
            const __half* vn = v16 + (j0 + BN) * DHEAD;
            uint32_t nK = OFF_K0 + (uint32_t)(bufit ^ 1) * 18432;
            uint32_t nV = OFF_V0 + (uint32_t)(bufit ^ 1) * 18432;
            #pragma unroll
            for (int it = 0; it < 4; it++) {
                int c = tid + it * 128;
                int row = c >> 3, c16 = (c & 7) * 8;
                uint32_t soff = (uint32_t)(row * KSTR + c16) * 2;
                CP16(sb + nK + soff, kn + row * DHEAD + c16);
                CP16(sb + nV + soff, vn + row * DHEAD + c16);
            }
            if (tid < 64)
                CP16(sb + OFF_B0 + (bufit ^ 1) * 1024 + tid * 16,
                     biasrow + (i0 - j0 - BN) - 64 + tid * 4);
        }
        CP_COMMIT();

        // --- S = q~ K~^T (each K ldmatrix feeds both row-frags) ---
        float sacc[2][32];
        #pragma unroll
        for (int r = 0; r < 2; r++)
            #pragma unroll
            for (int i = 0; i < 32; i++) sacc[r][i] = 0.0f;

        #pragma unroll
        for (int kk = 0; kk < 4; kk++) {
            #pragma unroll
            for (int t2 = 0; t2 < 4; t2++) {
                int key = 16 * t2 + ((g >> 1) << 3) + gr;
                int d0  = 16 * kk + ((g & 1) << 3);
                uint32_t off = (uint32_t)(key * KSTR + d0) * 2;
                uint32_t kb[4];
                LDSM4(kb, sb + offK + off);
                #pragma unroll
                for (int r = 0; r < 2; r++) {
                    float* dA = sacc[r] + 8 * t2;
                    float* dB = sacc[r] + 8 * t2 + 4;
                    MMAH(dA, qf[r][kk], kb[0], kb[1]);
                    MMAH(dB, qf[r][kk], kb[2], kb[3]);
                }
            }
        }

        // --- bias add (always) ---
        #pragma unroll
        for (int r = 0; r < 2; r++) {
            int rA = ri0 + 16 * r;
            #pragma unroll
            for (int n = 0; n < 8; n++) {
                int cj = 8 * n + qc2;
                sacc[r][4 * n + 0] += sB[rA - cj + 64];
                sacc[r][4 * n + 1] += sB[rA - cj + 63];
                sacc[r][4 * n + 2] += sB[rA - cj + 72];
                sacc[r][4 * n + 3] += sB[rA - cj + 71];
            }
        }
        // --- key mask only on the tile straddling L (uniform branch) ---
        if (j0 + BN > L) {
            #pragma unroll
            for (int r = 0; r < 2; r++) {
                #pragma unroll
                for (int n = 0; n < 8; n++) {
                    int cj = 8 * n + qc2;
                    bool in0 = (j0 + cj)     < L;
                    bool in1 = (j0 + cj + 1) < L;
                    if (!in0) { sacc[r][4 * n + 0] = -1e9f; sacc[r][4 * n + 2] = -1e9f; }
                    if (!in1) { sacc[r][4 * n + 1] = -1e9f; sacc[r][4 * n + 3] = -1e9f; }
                }
            }
        }

        // --- lazy frame check: local maxes + one warp vote ---
        float lm[4];
        #pragma unroll
        for (int r = 0; r < 2; r++) {
            float a0 = -1e30f, a1 = -1e30f;
            #pragma unroll
            for (int n = 0; n < 8; n++) {
                a0 = fmaxf(a0, fmaxf(sacc[r][4 * n + 0], sacc[r][4 * n + 1]));
                a1 = fmaxf(a1, fmaxf(sacc[r][4 * n + 2], sacc[r][4 * n + 3]));
            }
            lm[2 * r] = a0; lm[2 * r + 1] = a1;
        }
        bool need = (lm[0] > mO[0] + 10.0f) || (lm[1] > mO[1] + 10.0f) ||
                    (lm[2] > mO[2] + 10.0f) || (lm[3] > mO[3] + 10.0f);
        if (__any_sync(0xffffffffu, need)) {
            #pragma unroll
            for (int g4 = 0; g4 < 4; g4++) {
                float mx = lm[g4];
                mx = fmaxf(mx, __shfl_xor_sync(0xffffffffu, mx, 1));
                mx = fmaxf(mx, __shfl_xor_sync(0xffffffffu, mx, 2));
                float mn = fmaxf(mO[g4], mx);
                float sc = ex2(mO[g4] - mn);
                lp[g4] *= sc;
                mO[g4] = mn;
                float* oa = oacc[g4 >> 1] + ((g4 & 1) ? 2 : 0);
                #pragma unroll
                for (int i = 0; i < 8; i++) {
                    oa[4 * i + 0] *= sc;
                    oa[4 * i + 1] *= sc;
                }
            }
        }

        // --- P = ex2.f16x2(s - m): MUFU halved, fragments built directly ---
        uint32_t pf[2][4][4];
        #pragma unroll
        for (int r = 0; r < 2; r++) {
            float f0 = mO[2 * r], f1 = mO[2 * r + 1];
            #pragma unroll
            for (int kk2 = 0; kk2 < 4; kk2++) {
                float* pa = sacc[r] + 8 * kk2;
                pf[r][kk2][0] = h2ex2(pa[0] - f0, pa[1] - f0);
                pf[r][kk2][1] = h2ex2(pa[2] - f1, pa[3] - f1);
                pf[r][kk2][2] = h2ex2(pa[4] - f0, pa[5] - f0);
                pf[r][kk2][3] = h2ex2(pa[6] - f1, pa[7] - f1);
            }
            // row sums from the SAME rounded P values (2-level HADD2 tree)
            uint32_t u0a = hadd2u(pf[r][0][0], pf[r][1][0]);
            uint32_t u0b = hadd2u(pf[r][2][0], pf[r][3][0]);
            uint32_t u0c = hadd2u(pf[r][0][2], pf[r][1][2]);
            uint32_t u0d = hadd2u(pf[r][2][2], pf[r][3][2]);
            float2 fa = h22f2(hadd2u(u0a, u0b));
            float2 fb = h22f2(hadd2u(u0c, u0d));
            lp[2 * r] += (fa.x + fa.y) + (fb.x + fb.y);
            uint32_t u1a = hadd2u(pf[r][0][1], pf[r][1][1]);
            uint32_t u1b = hadd2u(pf[r][2][1], pf[r][3][1]);
            uint32_t u1c = hadd2u(pf[r][0][3], pf[r][1][3]);
            uint32_t u1d = hadd2u(pf[r][2][3], pf[r][3][3]);
            float2 fc = h22f2(hadd2u(u1a, u1b));
            float2 fd = h22f2(hadd2u(u1c, u1d));
            lp[2 * r + 1] += (fc.x + fc.y) + (fd.x + fd.y);
        }

        // --- O += P V~ : uninterrupted MMA stream ---
        #pragma unroll
        for (int kk2 = 0; kk2 < 4; kk2++) {
            int key = 16 * kk2 + ((g & 1) << 3) + gr;
            #pragma unroll
            for (int t2 = 0; t2 < 4; t2++) {
                int d0 = 16 * t2 + ((g >> 1) << 3);
                uint32_t off = (uint32_t)(key * KSTR + d0) * 2;
                uint32_t vb[4];
                LDSM4T(vb, sb + offV + off);
                #pragma unroll
                for (int r = 0; r < 2; r++) {
                    float* oA = oacc[r] + 8 * t2;
                    float* oB = oacc[r] + 8 * t2 + 4;
                    MMAH(oA, pf[r][kk2], vb[0], vb[1]);
                    MMAH(oB, pf[r][kk2], vb[2], vb[3]);
                }
            }
        }

        // --- make next tile resident & visible (single barrier per tile) ---
        CP_WAIT0();
        __syncthreads();
    }

    // --- epilogue: reduce l across quad, normalize, store ---
    float inv[4];
    #pragma unroll
    for (int g4 = 0; g4 < 4; g4++) {
        float s = lp[g4];
        s += __shfl_xor_sync(0xffffffffu, s, 1);
        s += __shfl_xor_sync(0xffffffffu, s, 2);
        inv[g4] = 1.0f / s;
    }
    #pragma unroll
    for (int r = 0; r < 2; r++) {
        int grow0 = i0 + ri0 + 16 * r;
        int grow1 = grow0 + 8;
        #pragma unroll
        for (int n = 0; n < 8; n++) {
            *(float2*)(oh + grow0 * DHEAD + 8 * n + qc2) =
                make_float2(oacc[r][4 * n + 0] * inv[2 * r],
                            oacc[r][4 * n + 1] * inv[2 * r]);
            *(float2*)(oh + grow1 * DHEAD + 8 * n + qc2) =
                make_float2(oacc[r][4 * n + 2] * inv[2 * r + 1],
                            oacc[r][4 * n + 3] * inv[2 * r + 1]);
        }
    }
}

// ---------------------------------------------------------------------------
extern "C" void kernel_launch(void* const* d_in, const int* in_sizes, int n_in,
                              void* d_out, int out_size) {
    const float* q          = (const float*)d_in[0];
    const float* k          = (const float*)d_in[1];
    const float* v          = (const float*)d_in[2];
    const float* bias_table = (const float*)d_in[3];
    const int*   event_len  = (const int*)d_in[4];
    float*       out        = (float*)d_out;

    (void)in_sizes; (void)n_in; (void)out_size;

    prep_kernel<<<(TOT / 4 + 255) / 256, 256>>>(k, v, bias_table);

    cudaFuncSetAttribute(attn_mma_kernel, cudaFuncAttributeMaxDynamicSharedMemorySize,
                         SMEM_TOTAL);

    dim3 grid(S_LEN / BM, NHEAD, NBATCH);
    attn_mma_kernel<<<grid, 128, SMEM_TOTAL>>>(q, event_len, out);
}